// round 14
// baseline (speedup 1.0000x reference)
#include <cuda_runtime.h>
#include <cuda_bf16.h>
#include <math.h>
#include <stdint.h>

#define Bz   4
#define Lz   1024
#define Dz   1024
#define Hz   16
#define HDz  64
#define Mz   (Bz*Lz)          // 4096
#define ORDERz 3
#define ZN   (Bz*Hz)          // 64

// ---------------- scratch (__device__ globals) ----------------------------------
__device__ __align__(16) float g_v[Mz*Dz];     // (B,H,L,hd) fp32
__device__ __align__(16) float g_bias[Lz];

__device__ __align__(16) __nv_bfloat16 g_xh[Mz*Dz], g_xl[Mz*Dz];
__device__ __align__(16) __nv_bfloat16 g_wh[4][Dz*Dz], g_wl[4][Dz*Dz]; // q,k,v,o
__device__ __align__(16) __nv_bfloat16 g_qh[Mz*Dz], g_ql[Mz*Dz];       // (B,H,L,hd)
__device__ __align__(16) __nv_bfloat16 g_kh[Mz*Dz], g_kl[Mz*Dz];       // (B,H,L,hd)
__device__ __align__(16) __nv_bfloat16 g_vth[Mz*Dz], g_vtl[Mz*Dz];     // (B,H,hd,L)
__device__ __align__(16) __nv_bfloat16 g_ch[Mz*Dz], g_cl[Mz*Dz];       // ctx (B,L,D)

// ---------------- PTX helpers ----------------------------------------------------
__device__ __forceinline__ uint32_t smem_u32(const void* p) {
    uint32_t a;
    asm("{ .reg .u64 t; cvta.to.shared.u64 t, %1; cvt.u32.u64 %0, t; }" : "=r"(a) : "l"(p));
    return a;
}
__device__ __forceinline__ void cpasync16(uint32_t s, const void* g) {
    asm volatile("cp.async.cg.shared.global [%0], [%1], 16;" :: "r"(s), "l"(g));
}
#define CP_COMMIT()  asm volatile("cp.async.commit_group;" ::: "memory")
#define CP_WAIT2()   asm volatile("cp.async.wait_group 2;" ::: "memory")
#define CP_WAIT1()   asm volatile("cp.async.wait_group 1;" ::: "memory")
#define CP_WAIT0()   asm volatile("cp.async.wait_group 0;" ::: "memory")

__device__ __forceinline__ void stg_cs_f2(float* p, float2 v) {
    asm volatile("st.global.cs.v2.f32 [%0], {%1, %2};" :: "l"(p), "f"(v.x), "f"(v.y) : "memory");
}
__device__ __forceinline__ float4 ldg_cs_f4(const float4* p) {
    float4 v;
    asm volatile("ld.global.cs.v4.f32 {%0,%1,%2,%3}, [%4];"
        : "=f"(v.x), "=f"(v.y), "=f"(v.z), "=f"(v.w) : "l"(p));
    return v;
}
__device__ __forceinline__ void stg_cs_f4(float4* p, float4 v) {
    asm volatile("st.global.cs.v4.f32 [%0], {%1,%2,%3,%4};"
        :: "l"(p), "f"(v.x), "f"(v.y), "f"(v.z), "f"(v.w) : "memory");
}

__device__ __forceinline__ void hmma(float* d, const uint32_t* a, const uint32_t* b) {
    asm volatile(
        "mma.sync.aligned.m16n8k16.row.col.f32.bf16.bf16.f32 "
        "{%0,%1,%2,%3}, {%4,%5,%6,%7}, {%8,%9}, {%0,%1,%2,%3};"
        : "+f"(d[0]), "+f"(d[1]), "+f"(d[2]), "+f"(d[3])
        : "r"(a[0]), "r"(a[1]), "r"(a[2]), "r"(a[3]), "r"(b[0]), "r"(b[1]));
}
__device__ __forceinline__ void ldsm_x4(uint32_t* r, uint32_t saddr) {
    asm volatile("ldmatrix.sync.aligned.m8n8.x4.shared.b16 {%0,%1,%2,%3}, [%4];"
        : "=r"(r[0]), "=r"(r[1]), "=r"(r[2]), "=r"(r[3]) : "r"(saddr));
}
__device__ __forceinline__ void ldsm_x2(uint32_t* r, uint32_t saddr) {
    asm volatile("ldmatrix.sync.aligned.m8n8.x2.shared.b16 {%0,%1}, [%2];"
        : "=r"(r[0]), "=r"(r[1]) : "r"(saddr));
}

__device__ __forceinline__ __nv_bfloat162 split_hi2(float x, float y,
                                                    __nv_bfloat162& lo2) {
    __nv_bfloat16 hx = __float2bfloat16(x);
    __nv_bfloat16 hy = __float2bfloat16(y);
    lo2 = __nv_bfloat162(__float2bfloat16(x - __bfloat162float(hx)),
                         __float2bfloat16(y - __bfloat162float(hy)));
    return __nv_bfloat162(hx, hy);
}

__device__ __forceinline__ uint32_t a_ldsm_off(int lane, int RS) {
    return (uint32_t)((lane & 7) * RS + ((lane >> 3) & 1) * 8 * RS + ((lane >> 4) & 1) * 16);
}
__device__ __forceinline__ uint32_t b_ldsm_off(int lane, int RS) {
    const int l = lane & 15;
    return (uint32_t)((l & 7) * RS + ((l >> 3) & 1) * 16);
}

// ---------------- 512-thread, 128x256-tile, 3-stage, single-barrier HMMA GEMM ------
#define KC 32
#define ROWB 80
#define G_AM (128 * ROWB)
#define G_BM (256 * ROWB)
#define G_STAGE (2 * G_AM + 2 * G_BM)    // 61440
#define GSMEM (3 * G_STAGE)              // 184320

template<int MODE>
__global__ __launch_bounds__(512, 1) void gemm512(
    const __nv_bfloat16* __restrict__ Ah, const __nv_bfloat16* __restrict__ Al,
    const __nv_bfloat16* __restrict__ whBase, const __nv_bfloat16* __restrict__ wlBase,
    const float* __restrict__ bq, const float* __restrict__ bk, const float* __restrict__ bv,
    __nv_bfloat16* __restrict__ qh, __nv_bfloat16* __restrict__ ql,
    __nv_bfloat16* __restrict__ kh, __nv_bfloat16* __restrict__ kl,
    float* __restrict__ Cf)
{
    extern __shared__ char sm[];
    const uint32_t sbase = smem_u32(sm);

    const int zz = (MODE == 1) ? blockIdx.z : 0;     // MODE 0: base pre-offset to Wo
    const size_t WN = (size_t)Dz * Dz;
    const __nv_bfloat16* Bh = whBase + (size_t)zz * WN;
    const __nv_bfloat16* Bl = wlBase + (size_t)zz * WN;
    const float* bias = (MODE == 0) ? bq : (blockIdx.z == 0) ? bq : (blockIdx.z == 1) ? bk : bv;

    const int K = Dz;
    const int tid  = threadIdx.x;
    const int warp = tid >> 5;
    const int lane = tid & 31;
    const int g = lane >> 2;
    const int t = lane & 3;
    const int wm = (warp >> 3) * 64;
    const int wn = (warp & 7) * 32;

    const int bm = blockIdx.y * 128;
    const int bn = blockIdx.x * 256;

    const __nv_bfloat16* tAh = Ah + (size_t)bm * K;
    const __nv_bfloat16* tAl = Al + (size_t)bm * K;
    const __nv_bfloat16* tBh = Bh + (size_t)bn * K;
    const __nv_bfloat16* tBl = Bl + (size_t)bn * K;

    const int ar = tid >> 2, as = tid & 3;

    const uint32_t aOff = a_ldsm_off(lane, ROWB);
    const uint32_t bOff = b_ldsm_off(lane, ROWB);

    auto prefetch = [&](int c, int stage) {
        const uint32_t sb = sbase + stage * G_STAGE;
        const int kb = c * KC;
        {
            const size_t go = (size_t)ar * K + kb + as * 8;
            const uint32_t so = ar * ROWB + as * 16;
            cpasync16(sb + so, tAh + go);
            cpasync16(sb + G_AM + so, tAl + go);
        }
        #pragma unroll
        for (int i = 0; i < 2; i++) {
            const int idx = tid + i * 512;
            const int row = idx >> 2, seg = idx & 3;
            const size_t go = (size_t)row * K + kb + seg * 8;
            const uint32_t so = row * ROWB + seg * 16;
            cpasync16(sb + 2 * G_AM + so, tBh + go);
            cpasync16(sb + 2 * G_AM + G_BM + so, tBl + go);
        }
    };

    float acc[4][4][4];
    #pragma unroll
    for (int i = 0; i < 4; i++)
        #pragma unroll
        for (int j = 0; j < 4; j++)
            #pragma unroll
            for (int k = 0; k < 4; k++) acc[i][j][k] = 0.0f;

    const int nch = K / KC;   // 32
    prefetch(0, 0); CP_COMMIT();
    prefetch(1, 1); CP_COMMIT();

    for (int c = 0; c < nch; c++) {
        if (c + 1 < nch) { CP_WAIT1(); } else { CP_WAIT0(); }
        __syncthreads();
        // prefetch chunk c+2 into stage (c+2)%3 == (c-1)%3: all readers of that
        // stage passed this barrier (they read it during iter c-1). One barrier
        // per chunk; copy overlaps this chunk's compute.
        if (c + 2 < nch) { prefetch(c + 2, (c + 2) % 3); }
        CP_COMMIT();

        const uint32_t sb  = sbase + (c % 3) * G_STAGE;
        const uint32_t sAh = sb;
        const uint32_t sAl = sb + G_AM;
        const uint32_t sBh = sb + 2 * G_AM;
        const uint32_t sBl = sb + 2 * G_AM + G_BM;

        #pragma unroll
        for (int kk = 0; kk < KC; kk += 16) {
            const uint32_t kb = kk * 2;

            uint32_t bH[4][2], bL[4][2];
            #pragma unroll
            for (int nt = 0; nt < 4; nt++) {
                const uint32_t ro = (wn + nt * 8) * ROWB + kb + bOff;
                ldsm_x2(bH[nt], sBh + ro);
                ldsm_x2(bL[nt], sBl + ro);
            }

            #pragma unroll
            for (int mt = 0; mt < 4; mt++) {
                const uint32_t ro = (wm + mt * 16) * ROWB + kb + aOff;
                uint32_t aH[4], aL[4];
                ldsm_x4(aH, sAh + ro);
                ldsm_x4(aL, sAl + ro);

                #pragma unroll
                for (int nt = 0; nt < 4; nt++) {
                    hmma(acc[mt][nt], aH, bH[nt]);
                    hmma(acc[mt][nt], aH, bL[nt]);
                    hmma(acc[mt][nt], aL, bH[nt]);
                }
            }
        }
    }

    #pragma unroll
    for (int mt = 0; mt < 4; mt++) {
        const int m0 = bm + wm + mt * 16 + g;
        #pragma unroll
        for (int nt = 0; nt < 4; nt++) {
            const int n0 = bn + wn + nt * 8 + 2 * t;
            const float b0 = bias[n0], b1 = bias[n0 + 1];
            float v0 = acc[mt][nt][0] + b0;
            float v1 = acc[mt][nt][1] + b1;
            float v2 = acc[mt][nt][2] + b0;
            float v3 = acc[mt][nt][3] + b1;
            if (MODE == 0) {
                *(float2*)&Cf[(size_t)m0 * Dz + n0]       = make_float2(v0, v1);
                *(float2*)&Cf[(size_t)(m0 + 8) * Dz + n0] = make_float2(v2, v3);
            } else {
                const int h = n0 >> 6, dd = n0 & 63;
                const int b = m0 >> 10, l = m0 & 1023;
                if (blockIdx.z == 2) {
                    float* base = Cf + (((size_t)(b * Hz + h) * Lz) << 6) + dd;
                    *(float2*)(base + ((size_t)l << 6))       = make_float2(v0, v1);
                    *(float2*)(base + ((size_t)(l + 8) << 6)) = make_float2(v2, v3);
                } else {
                    __nv_bfloat16* Ch = (blockIdx.z == 0) ? qh : kh;
                    __nv_bfloat16* Cl = (blockIdx.z == 0) ? ql : kl;
                    const size_t i0 = (((size_t)(b * Hz + h) * Lz + l)     << 6) + dd;
                    const size_t i1 = (((size_t)(b * Hz + h) * Lz + l + 8) << 6) + dd;
                    __nv_bfloat162 lo;
                    __nv_bfloat162 hi = split_hi2(v0, v1, lo);
                    *(__nv_bfloat162*)&Ch[i0] = hi;
                    *(__nv_bfloat162*)&Cl[i0] = lo;
                    hi = split_hi2(v2, v3, lo);
                    *(__nv_bfloat162*)&Ch[i1] = hi;
                    *(__nv_bfloat162*)&Cl[i1] = lo;
                }
            }
        }
    }
}

// ---------------- scores HMMA (streaming stores, unchanged R13) ---------------------
#define SROW 144
#define SMAT (128 * SROW)
#define SSMEM (4 * SMAT)       // 73728

__global__ __launch_bounds__(256, 2) void scores_hmma(
    const __nv_bfloat16* __restrict__ qh, const __nv_bfloat16* __restrict__ ql,
    const __nv_bfloat16* __restrict__ kh, const __nv_bfloat16* __restrict__ kl,
    const float* __restrict__ bias, float* __restrict__ attn)
{
    extern __shared__ char sm[];
    const uint32_t sbase = smem_u32(sm);

    const int tid  = threadIdx.x;
    const int warp = tid >> 5;
    const int lane = tid & 31;
    const int g = lane >> 2;
    const int t = lane & 3;
    const int wm = (warp >> 2) * 64;
    const int wn = (warp & 3) * 32;

    const int z  = blockIdx.z;
    const int bm = blockIdx.y * 128;
    const int bn = blockIdx.x * 128;

    const size_t zofs = (size_t)z * Lz * HDz;
    const __nv_bfloat16* pqh = qh + zofs + (size_t)bm * HDz;
    const __nv_bfloat16* pql = ql + zofs + (size_t)bm * HDz;
    const __nv_bfloat16* pkh = kh + zofs + (size_t)bn * HDz;
    const __nv_bfloat16* pkl = kl + zofs + (size_t)bn * HDz;

    #pragma unroll
    for (int i = 0; i < 4; i++) {
        const int idx = tid + i * 256;
        const int row = idx >> 3, seg = idx & 7;
        const uint32_t off = row * SROW + seg * 16;
        const size_t go = (size_t)row * HDz + seg * 8;
        cpasync16(sbase + 0 * SMAT + off, pqh + go);
        cpasync16(sbase + 1 * SMAT + off, pql + go);
        cpasync16(sbase + 2 * SMAT + off, pkh + go);
        cpasync16(sbase + 3 * SMAT + off, pkl + go);
    }
    CP_COMMIT();
    CP_WAIT0();
    __syncthreads();

    float acc[4][4][4];
    #pragma unroll
    for (int i = 0; i < 4; i++)
        #pragma unroll
        for (int j = 0; j < 4; j++)
            #pragma unroll
            for (int k = 0; k < 4; k++) acc[i][j][k] = 0.0f;

    const uint32_t sQh = sbase;
    const uint32_t sQl = sbase + 1 * SMAT;
    const uint32_t sKh = sbase + 2 * SMAT;
    const uint32_t sKl = sbase + 3 * SMAT;

    const uint32_t aOff = a_ldsm_off(lane, SROW);
    const uint32_t bOff = b_ldsm_off(lane, SROW);

    #pragma unroll
    for (int kk = 0; kk < 64; kk += 16) {
        const uint32_t kb = kk * 2;

        uint32_t bH[4][2], bL[4][2];
        #pragma unroll
        for (int nt = 0; nt < 4; nt++) {
            const uint32_t ro = (wn + nt * 8) * SROW + kb + bOff;
            ldsm_x2(bH[nt], sKh + ro);
            ldsm_x2(bL[nt], sKl + ro);
        }

        #pragma unroll
        for (int mt = 0; mt < 4; mt++) {
            const uint32_t ro = (wm + mt * 16) * SROW + kb + aOff;
            uint32_t aH[4], aL[4];
            ldsm_x4(aH, sQh + ro);
            ldsm_x4(aL, sQl + ro);

            #pragma unroll
            for (int nt = 0; nt < 4; nt++) {
                hmma(acc[mt][nt], aH, bH[nt]);
                hmma(acc[mt][nt], aH, bL[nt]);
                hmma(acc[mt][nt], aL, bH[nt]);
            }
        }
    }

    float* attnZ = attn + (size_t)z * Lz * Lz;
    #pragma unroll
    for (int mt = 0; mt < 4; mt++) {
        const int m0 = bm + wm + mt * 16 + g;
        #pragma unroll
        for (int nt = 0; nt < 4; nt++) {
            const int n0 = bn + wn + nt * 8 + 2 * t;
            const float b0 = bias[n0], b1 = bias[n0 + 1];
            stg_cs_f2(&attnZ[(size_t)m0 * Lz + n0],
                      make_float2(acc[mt][nt][0] * 0.125f + b0, acc[mt][nt][1] * 0.125f + b1));
            stg_cs_f2(&attnZ[(size_t)(m0 + 8) * Lz + n0],
                      make_float2(acc[mt][nt][2] * 0.125f + b0, acc[mt][nt][3] * 0.125f + b1));
        }
    }
}

// ---------------- softmax: no-max, streaming (unchanged R13) --------------------------
__global__ __launch_bounds__(256) void softmax_kernel(float* __restrict__ attn)
{
    const size_t row = blockIdx.x;
    float4* p = reinterpret_cast<float4*>(attn + row * Lz);
    const int tid = threadIdx.x;
    __shared__ float red[8];

    float4 v = ldg_cs_f4(p + tid);
    v.x = __expf(v.x); v.y = __expf(v.y);
    v.z = __expf(v.z); v.w = __expf(v.w);
    float s = v.x + v.y + v.z + v.w;
    #pragma unroll
    for (int o = 16; o > 0; o >>= 1) s += __shfl_xor_sync(0xFFFFFFFFu, s, o);
    if ((tid & 31) == 0) red[tid >> 5] = s;
    __syncthreads();
    s = red[0];
    #pragma unroll
    for (int i = 1; i < 8; i++) s += red[i];

    const float inv = 1.0f / s;
    v.x *= inv; v.y *= inv; v.z *= inv; v.w *= inv;
    stg_cs_f4(p + tid, v);
}

// ---------------- AV HMMA (unchanged R13) --------------------------------------------
#define AVF_ROW 144
#define AVF_BYTES (128 * AVF_ROW)
#define AV_HROW 80
#define AV_HBYTES (128 * AV_HROW)
#define AV_VBYTES (64 * AV_HROW)
#define AV_AH_OFF (2 * AVF_BYTES)
#define AV_AL_OFF (AV_AH_OFF + AV_HBYTES)
#define AV_V_OFF  (AV_AL_OFF + AV_HBYTES)
#define AVSMEM (AV_V_OFF + 4 * AV_VBYTES)    // 77824

__global__ __launch_bounds__(256, 2) void av_hmma(
    const float* __restrict__ attn,
    const __nv_bfloat16* __restrict__ vth, const __nv_bfloat16* __restrict__ vtl,
    __nv_bfloat16* __restrict__ Ch, __nv_bfloat16* __restrict__ Cl)
{
    extern __shared__ char sm[];
    const uint32_t sbase = smem_u32(sm);

    const int tid  = threadIdx.x;
    const int warp = tid >> 5;
    const int lane = tid & 31;
    const int g = lane >> 2;
    const int t = lane & 3;
    const int wm = (warp >> 1) * 32;
    const int wn = (warp & 1) * 32;

    const int z  = blockIdx.z;
    const int bm = blockIdx.y * 128;

    const float* pA = attn + (size_t)z * Lz * Lz + (size_t)bm * Lz;
    const __nv_bfloat16* pvh = vth + (size_t)z * HDz * Lz;
    const __nv_bfloat16* pvl = vtl + (size_t)z * HDz * Lz;

    const uint32_t sAh = sbase + AV_AH_OFF;
    const uint32_t sAl = sbase + AV_AL_OFF;
    const uint32_t sV  = sbase + AV_V_OFF;

    const uint32_t aOff = a_ldsm_off(lane, AV_HROW);
    const uint32_t bOff = b_ldsm_off(lane, AV_HROW);

    const int arow = tid >> 3, aseg = tid & 7;
    const int vrow = tid >> 2, vseg = tid & 3;

    auto prefetch = [&](int c, int stage) {
        const uint32_t sa = sbase + stage * AVF_BYTES;
        #pragma unroll
        for (int i = 0; i < 4; i++) {
            const int row = arow + i * 32;
            cpasync16(sa + row * AVF_ROW + aseg * 16,
                      pA + (size_t)row * Lz + c * 32 + aseg * 4);
        }
        const uint32_t sv = sV + stage * (2 * AV_VBYTES);
        cpasync16(sv + vrow * AV_HROW + vseg * 16,
                  pvh + (size_t)vrow * Lz + c * 32 + vseg * 8);
        cpasync16(sv + AV_VBYTES + vrow * AV_HROW + vseg * 16,
                  pvl + (size_t)vrow * Lz + c * 32 + vseg * 8);
    };

    float acc[2][4][4];
    #pragma unroll
    for (int i = 0; i < 2; i++)
        #pragma unroll
        for (int j = 0; j < 4; j++)
            #pragma unroll
            for (int k = 0; k < 4; k++) acc[i][j][k] = 0.0f;

    const int nch = Lz / 32;
    prefetch(0, 0); CP_COMMIT();
    prefetch(1, 1); CP_COMMIT();

    for (int c = 0; c < nch; c++) {
        if (c + 1 < nch) { CP_WAIT1(); } else { CP_WAIT0(); }
        __syncthreads();

        const uint32_t sa = sbase + (c & 1) * AVF_BYTES;
        #pragma unroll
        for (int i = 0; i < 4; i++) {
            const int row = arow + i * 32;
            const float4 v = *(const float4*)(sm + (sa - sbase) + row * AVF_ROW + aseg * 16);
            __nv_bfloat162 lo0, lo1;
            __nv_bfloat162 hi0 = split_hi2(v.x, v.y, lo0);
            __nv_bfloat162 hi1 = split_hi2(v.z, v.w, lo1);
            uint2 h8, l8;
            h8.x = *reinterpret_cast<uint32_t*>(&hi0);
            h8.y = *reinterpret_cast<uint32_t*>(&hi1);
            l8.x = *reinterpret_cast<uint32_t*>(&lo0);
            l8.y = *reinterpret_cast<uint32_t*>(&lo1);
            *(uint2*)(sm + AV_AH_OFF + row * AV_HROW + aseg * 8) = h8;
            *(uint2*)(sm + AV_AL_OFF + row * AV_HROW + aseg * 8) = l8;
        }
        __syncthreads();

        const uint32_t sVh = sV + (c & 1) * (2 * AV_VBYTES);
        const uint32_t sVl = sVh + AV_VBYTES;

        #pragma unroll
        for (int kk = 0; kk < 32; kk += 16) {
            const uint32_t kb = kk * 2;

            uint32_t bH[4][2], bL[4][2];
            #pragma unroll
            for (int nt = 0; nt < 4; nt++) {
                const uint32_t ro = (wn + nt * 8) * AV_HROW + kb + bOff;
                ldsm_x2(bH[nt], sVh + ro);
                ldsm_x2(bL[nt], sVl + ro);
            }

            #pragma unroll
            for (int mt = 0; mt < 2; mt++) {
                const uint32_t ro = (wm + mt * 16) * AV_HROW + kb + aOff;
                uint32_t aH[4], aL[4];
                ldsm_x4(aH, sAh + ro);
                ldsm_x4(aL, sAl + ro);

                #pragma unroll
                for (int nt = 0; nt < 4; nt++) {
                    hmma(acc[mt][nt], aH, bH[nt]);
                    hmma(acc[mt][nt], aH, bL[nt]);
                    hmma(acc[mt][nt], aL, bH[nt]);
                }
            }
        }

        __syncthreads();
        if (c + 2 < nch) { prefetch(c + 2, (c & 1)); CP_COMMIT(); }
        else { CP_COMMIT(); }
    }

    const int b = z >> 4, h = z & 15;
    #pragma unroll
    for (int mt = 0; mt < 2; mt++) {
        const int m0 = bm + wm + mt * 16 + g;
        #pragma unroll
        for (int nt = 0; nt < 4; nt++) {
            const int n0 = wn + nt * 8 + 2 * t;
            const size_t i0 = ((size_t)(b * Lz + m0)     << 10) + h * HDz + n0;
            const size_t i1 = ((size_t)(b * Lz + m0 + 8) << 10) + h * HDz + n0;
            __nv_bfloat162 lo;
            __nv_bfloat162 hi = split_hi2(acc[mt][nt][0], acc[mt][nt][1], lo);
            *(__nv_bfloat162*)&Ch[i0] = hi;
            *(__nv_bfloat162*)&Cl[i0] = lo;
            hi = split_hi2(acc[mt][nt][2], acc[mt][nt][3], lo);
            *(__nv_bfloat162*)&Ch[i1] = hi;
            *(__nv_bfloat162*)&Cl[i1] = lo;
        }
    }
}

// ---------------- V transpose + split ------------------------------------------------
__global__ __launch_bounds__(256) void tsplit_v(
    const float* __restrict__ v, __nv_bfloat16* __restrict__ vth,
    __nv_bfloat16* __restrict__ vtl)
{
    __shared__ float tile[32][33];
    const int z  = blockIdx.z;
    const int l0 = blockIdx.x * 32;
    const int d0 = blockIdx.y * 32;
    const int tx = threadIdx.x & 31;
    const int ty = threadIdx.x >> 5;

    const float* src = v + (size_t)z * Lz * HDz;
    #pragma unroll
    for (int j = 0; j < 4; j++)
        tile[ty + j * 8][tx] = src[(size_t)(l0 + ty + j * 8) * HDz + d0 + tx];
    __syncthreads();

    __nv_bfloat16* dh = vth + (size_t)z * HDz * Lz;
    __nv_bfloat16* dl = vtl + (size_t)z * HDz * Lz;
    #pragma unroll
    for (int j = 0; j < 4; j++) {
        const float val = tile[tx][ty + j * 8];
        const __nv_bfloat16 h = __float2bfloat16(val);
        const size_t o = (size_t)(d0 + ty + j * 8) * Lz + l0 + tx;
        dh[o] = h;
        dl[o] = __float2bfloat16(val - __bfloat162float(h));
    }
}

// ---------------- misc small kernels --------------------------------------------------
__global__ __launch_bounds__(256) void split_kernel(
    const float* __restrict__ in, __nv_bfloat16* __restrict__ hi,
    __nv_bfloat16* __restrict__ lo, int n4)
{
    int i = blockIdx.x * (blockDim.x * 4) + threadIdx.x;
    #pragma unroll
    for (int u = 0; u < 4; u++, i += 256) {
        if (i < n4) {
            float4 v = ((const float4*)in)[i];
            __nv_bfloat162* H = (__nv_bfloat162*)hi;
            __nv_bfloat162* L = (__nv_bfloat162*)lo;
            __nv_bfloat162 l2;
            H[i*2+0] = split_hi2(v.x, v.y, l2); L[i*2+0] = l2;
            H[i*2+1] = split_hi2(v.z, v.w, l2); L[i*2+1] = l2;
        }
    }
}

__global__ __launch_bounds__(256) void wsplit4_kernel(
    const float* __restrict__ W0, const float* __restrict__ W1,
    const float* __restrict__ W2, const float* __restrict__ W3,
    __nv_bfloat16* __restrict__ hi, __nv_bfloat16* __restrict__ lo)
{
    const int z = blockIdx.z;
    const float* src = (z == 0) ? W0 : (z == 1) ? W1 : (z == 2) ? W2 : W3;
    const size_t WN = (size_t)Dz * Dz;
    __nv_bfloat162* H = (__nv_bfloat162*)(hi + z * WN);
    __nv_bfloat162* L = (__nv_bfloat162*)(lo + z * WN);
    int i = blockIdx.x * (blockDim.x * 4) + threadIdx.x;
    #pragma unroll
    for (int u = 0; u < 4; u++, i += 256) {
        float4 v = ((const float4*)src)[i];
        __nv_bfloat162 l2;
        H[i*2+0] = split_hi2(v.x, v.y, l2); L[i*2+0] = l2;
        H[i*2+1] = split_hi2(v.z, v.w, l2); L[i*2+1] = l2;
    }
}

__global__ void bias_energy_kernel(const float* __restrict__ field,
                                   const float* __restrict__ strength,
                                   float* __restrict__ bias,
                                   float* __restrict__ e)
{
    if (blockIdx.x == 4) {
        if (threadIdx.x == 0)
            e[0] = (strength[0] * strength[0] + strength[1] * strength[1] +
                    strength[2] * strength[2]) * (1.0f / 3.0f);
        return;
    }
    int m = blockIdx.x * blockDim.x + threadIdx.x;
    if (m < Lz) {
        const float pi = 3.14159265358979323846f;
        float acc = 0.0f;
        #pragma unroll
        for (int i = 0; i < ORDERz; i++) {
            float sig = 1.0f / (1.0f + expf(-field[i * Lz + m]));
            acc += strength[i] * sinf((float)m * (float)(i + 1) * pi / (float)Lz) * sig;
        }
        bias[m] = acc;
    }
}

// ---------------- launch ----------------------------------------------------------------
extern "C" void kernel_launch(void* const* d_in, const int* in_sizes, int n_in,
                              void* d_out, int out_size)
{
    const float* x  = (const float*)d_in[0];
    const float* Wq = (const float*)d_in[1];
    const float* bq = (const float*)d_in[2];
    const float* Wk = (const float*)d_in[3];
    const float* bk = (const float*)d_in[4];
    const float* Wv = (const float*)d_in[5];
    const float* bv = (const float*)d_in[6];
    const float* Wo = (const float*)d_in[7];
    const float* bo = (const float*)d_in[8];
    const float* tf = (const float*)d_in[9];
    const float* ts = (const float*)d_in[10];

    float* out    = (float*)d_out;
    float* attn   = out + (size_t)Bz * Lz * Dz;
    float* energy = attn + (size_t)ZN * Lz * Lz;

    float *gv, *gbias;
    cudaGetSymbolAddress((void**)&gv,    g_v);
    cudaGetSymbolAddress((void**)&gbias, g_bias);

    __nv_bfloat16 *xh, *xl, *wh, *wl, *qh, *ql, *kh, *kl, *vth, *vtl, *ch, *cl;
    cudaGetSymbolAddress((void**)&xh,  g_xh);
    cudaGetSymbolAddress((void**)&xl,  g_xl);
    cudaGetSymbolAddress((void**)&wh,  g_wh);
    cudaGetSymbolAddress((void**)&wl,  g_wl);
    cudaGetSymbolAddress((void**)&qh,  g_qh);
    cudaGetSymbolAddress((void**)&ql,  g_ql);
    cudaGetSymbolAddress((void**)&kh,  g_kh);
    cudaGetSymbolAddress((void**)&kl,  g_kl);
    cudaGetSymbolAddress((void**)&vth, g_vth);
    cudaGetSymbolAddress((void**)&vtl, g_vtl);
    cudaGetSymbolAddress((void**)&ch,  g_ch);
    cudaGetSymbolAddress((void**)&cl,  g_cl);

    cudaFuncSetAttribute(gemm512<0>,  cudaFuncAttributeMaxDynamicSharedMemorySize, GSMEM);
    cudaFuncSetAttribute(gemm512<1>,  cudaFuncAttributeMaxDynamicSharedMemorySize, GSMEM);
    cudaFuncSetAttribute(scores_hmma, cudaFuncAttributeMaxDynamicSharedMemorySize, SSMEM);
    cudaFuncSetAttribute(av_hmma,     cudaFuncAttributeMaxDynamicSharedMemorySize, AVSMEM);

    bias_energy_kernel<<<5, 256>>>(tf, ts, gbias, energy);

    const size_t WN = (size_t)Dz * Dz;
    split_kernel<<<(Mz*Dz/4 + 1023)/1024, 256>>>(x, xh, xl, Mz*Dz/4);
    wsplit4_kernel<<<dim3((WN/4)/1024, 1, 4), 256>>>(Wq, Wk, Wv, Wo, wh, wl);

    gemm512<1><<<dim3(Dz/256, Mz/128, 3), 512, GSMEM>>>(
        xh, xl, wh, wl, bq, bk, bv, qh, ql, kh, kl, gv);

    tsplit_v<<<dim3(Lz/32, HDz/32, ZN), 256>>>(gv, vth, vtl);

    scores_hmma<<<dim3(8, 8, ZN), 256, SSMEM>>>(qh, ql, kh, kl, gbias, attn);

    softmax_kernel<<<ZN * Lz, 256>>>(attn);

    av_hmma<<<dim3(1, Lz/128, ZN), 256, AVSMEM>>>(attn, vth, vtl, ch, cl);

    gemm512<0><<<dim3(Dz/256, Mz/128), 512, GSMEM>>>(
        ch, cl, wh + 3*WN, wl + 3*WN, bo, nullptr, nullptr,
        nullptr, nullptr, nullptr, nullptr, out);
}

// round 15
// speedup vs baseline: 1.0129x; 1.0129x over previous
#include <cuda_runtime.h>
#include <cuda_bf16.h>
#include <math.h>
#include <stdint.h>

#define Bz   4
#define Lz   1024
#define Dz   1024
#define Hz   16
#define HDz  64
#define Mz   (Bz*Lz)          // 4096
#define ORDERz 3
#define ZN   (Bz*Hz)          // 64

// ---------------- scratch (__device__ globals) ----------------------------------
__device__ __align__(16) float g_v[Mz*Dz];     // (B,H,L,hd) fp32
__device__ __align__(16) float g_bias[Lz];

__device__ __align__(16) __nv_bfloat16 g_xh[Mz*Dz], g_xl[Mz*Dz];
__device__ __align__(16) __nv_bfloat16 g_wh[4][Dz*Dz], g_wl[4][Dz*Dz]; // q,k,v,o
__device__ __align__(16) __nv_bfloat16 g_qh[Mz*Dz], g_ql[Mz*Dz];       // (B,H,L,hd)
__device__ __align__(16) __nv_bfloat16 g_kh[Mz*Dz], g_kl[Mz*Dz];       // (B,H,L,hd)
__device__ __align__(16) __nv_bfloat16 g_vth[Mz*Dz], g_vtl[Mz*Dz];     // (B,H,hd,L)
__device__ __align__(16) __nv_bfloat16 g_ch[Mz*Dz], g_cl[Mz*Dz];       // ctx (B,L,D)

// ---------------- PTX helpers ----------------------------------------------------
__device__ __forceinline__ uint32_t smem_u32(const void* p) {
    uint32_t a;
    asm("{ .reg .u64 t; cvta.to.shared.u64 t, %1; cvt.u32.u64 %0, t; }" : "=r"(a) : "l"(p));
    return a;
}
__device__ __forceinline__ void cpasync16(uint32_t s, const void* g) {
    asm volatile("cp.async.cg.shared.global [%0], [%1], 16;" :: "r"(s), "l"(g));
}
#define CP_COMMIT()  asm volatile("cp.async.commit_group;" ::: "memory")
#define CP_WAIT2()   asm volatile("cp.async.wait_group 2;" ::: "memory")
#define CP_WAIT1()   asm volatile("cp.async.wait_group 1;" ::: "memory")
#define CP_WAIT0()   asm volatile("cp.async.wait_group 0;" ::: "memory")

__device__ __forceinline__ void stg_cs_f2(float* p, float2 v) {
    asm volatile("st.global.cs.v2.f32 [%0], {%1, %2};" :: "l"(p), "f"(v.x), "f"(v.y) : "memory");
}
__device__ __forceinline__ float4 ldg_cs_f4(const float4* p) {
    float4 v;
    asm volatile("ld.global.cs.v4.f32 {%0,%1,%2,%3}, [%4];"
        : "=f"(v.x), "=f"(v.y), "=f"(v.z), "=f"(v.w) : "l"(p));
    return v;
}
__device__ __forceinline__ void stg_cs_f4(float4* p, float4 v) {
    asm volatile("st.global.cs.v4.f32 [%0], {%1,%2,%3,%4};"
        :: "l"(p), "f"(v.x), "f"(v.y), "f"(v.z), "f"(v.w) : "memory");
}

__device__ __forceinline__ void hmma(float* d, const uint32_t* a, const uint32_t* b) {
    asm volatile(
        "mma.sync.aligned.m16n8k16.row.col.f32.bf16.bf16.f32 "
        "{%0,%1,%2,%3}, {%4,%5,%6,%7}, {%8,%9}, {%0,%1,%2,%3};"
        : "+f"(d[0]), "+f"(d[1]), "+f"(d[2]), "+f"(d[3])
        : "r"(a[0]), "r"(a[1]), "r"(a[2]), "r"(a[3]), "r"(b[0]), "r"(b[1]));
}
__device__ __forceinline__ void ldsm_x4(uint32_t* r, uint32_t saddr) {
    asm volatile("ldmatrix.sync.aligned.m8n8.x4.shared.b16 {%0,%1,%2,%3}, [%4];"
        : "=r"(r[0]), "=r"(r[1]), "=r"(r[2]), "=r"(r[3]) : "r"(saddr));
}
__device__ __forceinline__ void ldsm_x2(uint32_t* r, uint32_t saddr) {
    asm volatile("ldmatrix.sync.aligned.m8n8.x2.shared.b16 {%0,%1}, [%2];"
        : "=r"(r[0]), "=r"(r[1]) : "r"(saddr));
}

__device__ __forceinline__ __nv_bfloat162 split_hi2(float x, float y,
                                                    __nv_bfloat162& lo2) {
    __nv_bfloat16 hx = __float2bfloat16(x);
    __nv_bfloat16 hy = __float2bfloat16(y);
    lo2 = __nv_bfloat162(__float2bfloat16(x - __bfloat162float(hx)),
                         __float2bfloat16(y - __bfloat162float(hy)));
    return __nv_bfloat162(hx, hy);
}

__device__ __forceinline__ uint32_t a_ldsm_off(int lane, int RS) {
    return (uint32_t)((lane & 7) * RS + ((lane >> 3) & 1) * 8 * RS + ((lane >> 4) & 1) * 16);
}
__device__ __forceinline__ uint32_t b_ldsm_off(int lane, int RS) {
    const int l = lane & 15;
    return (uint32_t)((l & 7) * RS + ((l >> 3) & 1) * 16);
}

// ---------------- 512-thread, 128x256-tile, 3-stage HMMA GEMM (R13 loop) -----------
#define KC 32
#define ROWB 80
#define G_AM (128 * ROWB)
#define G_BM (256 * ROWB)
#define G_STAGE (2 * G_AM + 2 * G_BM)    // 61440
#define GSMEM (3 * G_STAGE)              // 184320

template<int MODE>
__global__ __launch_bounds__(512, 1) void gemm512(
    const __nv_bfloat16* __restrict__ Ah, const __nv_bfloat16* __restrict__ Al,
    const __nv_bfloat16* __restrict__ whBase, const __nv_bfloat16* __restrict__ wlBase,
    const float* __restrict__ bq, const float* __restrict__ bk, const float* __restrict__ bv,
    __nv_bfloat16* __restrict__ qh, __nv_bfloat16* __restrict__ ql,
    __nv_bfloat16* __restrict__ kh, __nv_bfloat16* __restrict__ kl,
    float* __restrict__ Cf)
{
    extern __shared__ char sm[];
    const uint32_t sbase = smem_u32(sm);

    const int zz = (MODE == 1) ? blockIdx.z : 0;     // MODE 0: base pre-offset to Wo
    const size_t WN = (size_t)Dz * Dz;
    const __nv_bfloat16* Bh = whBase + (size_t)zz * WN;
    const __nv_bfloat16* Bl = wlBase + (size_t)zz * WN;
    const float* bias = (MODE == 0) ? bq : (blockIdx.z == 0) ? bq : (blockIdx.z == 1) ? bk : bv;

    const int K = Dz;
    const int tid  = threadIdx.x;
    const int warp = tid >> 5;
    const int lane = tid & 31;
    const int g = lane >> 2;
    const int t = lane & 3;
    const int wm = (warp >> 3) * 64;
    const int wn = (warp & 7) * 32;

    const int bm = blockIdx.y * 128;
    const int bn = blockIdx.x * 256;

    const __nv_bfloat16* tAh = Ah + (size_t)bm * K;
    const __nv_bfloat16* tAl = Al + (size_t)bm * K;
    const __nv_bfloat16* tBh = Bh + (size_t)bn * K;
    const __nv_bfloat16* tBl = Bl + (size_t)bn * K;

    const int ar = tid >> 2, as = tid & 3;

    const uint32_t aOff = a_ldsm_off(lane, ROWB);
    const uint32_t bOff = b_ldsm_off(lane, ROWB);

    auto prefetch = [&](int c, int stage) {
        const uint32_t sb = sbase + stage * G_STAGE;
        const int kb = c * KC;
        {
            const size_t go = (size_t)ar * K + kb + as * 8;
            const uint32_t so = ar * ROWB + as * 16;
            cpasync16(sb + so, tAh + go);
            cpasync16(sb + G_AM + so, tAl + go);
        }
        #pragma unroll
        for (int i = 0; i < 2; i++) {
            const int idx = tid + i * 512;
            const int row = idx >> 2, seg = idx & 3;
            const size_t go = (size_t)row * K + kb + seg * 8;
            const uint32_t so = row * ROWB + seg * 16;
            cpasync16(sb + 2 * G_AM + so, tBh + go);
            cpasync16(sb + 2 * G_AM + G_BM + so, tBl + go);
        }
    };

    float acc[4][4][4];
    #pragma unroll
    for (int i = 0; i < 4; i++)
        #pragma unroll
        for (int j = 0; j < 4; j++)
            #pragma unroll
            for (int k = 0; k < 4; k++) acc[i][j][k] = 0.0f;

    const int nch = K / KC;   // 32
    prefetch(0, 0); CP_COMMIT();
    prefetch(1, 1); CP_COMMIT();
    prefetch(2, 2); CP_COMMIT();

    for (int c = 0; c < nch; c++) {
        if (c + 2 < nch) { CP_WAIT2(); }
        else if (c + 1 < nch) { CP_WAIT1(); }
        else { CP_WAIT0(); }
        __syncthreads();

        const int st = c % 3;
        const uint32_t sb  = sbase + st * G_STAGE;
        const uint32_t sAh = sb;
        const uint32_t sAl = sb + G_AM;
        const uint32_t sBh = sb + 2 * G_AM;
        const uint32_t sBl = sb + 2 * G_AM + G_BM;

        #pragma unroll
        for (int kk = 0; kk < KC; kk += 16) {
            const uint32_t kb = kk * 2;

            uint32_t bH[4][2], bL[4][2];
            #pragma unroll
            for (int nt = 0; nt < 4; nt++) {
                const uint32_t ro = (wn + nt * 8) * ROWB + kb + bOff;
                ldsm_x2(bH[nt], sBh + ro);
                ldsm_x2(bL[nt], sBl + ro);
            }

            #pragma unroll
            for (int mt = 0; mt < 4; mt++) {
                const uint32_t ro = (wm + mt * 16) * ROWB + kb + aOff;
                uint32_t aH[4], aL[4];
                ldsm_x4(aH, sAh + ro);
                ldsm_x4(aL, sAl + ro);

                // term passes: consecutive HMMAs hit different accumulators
                #pragma unroll
                for (int nt = 0; nt < 4; nt++) hmma(acc[mt][nt], aH, bH[nt]);
                #pragma unroll
                for (int nt = 0; nt < 4; nt++) hmma(acc[mt][nt], aH, bL[nt]);
                #pragma unroll
                for (int nt = 0; nt < 4; nt++) hmma(acc[mt][nt], aL, bH[nt]);
            }
        }

        __syncthreads();
        if (c + 3 < nch) { prefetch(c + 3, st); }
        CP_COMMIT();
    }

    #pragma unroll
    for (int mt = 0; mt < 4; mt++) {
        const int m0 = bm + wm + mt * 16 + g;
        #pragma unroll
        for (int nt = 0; nt < 4; nt++) {
            const int n0 = bn + wn + nt * 8 + 2 * t;
            const float b0 = bias[n0], b1 = bias[n0 + 1];
            float v0 = acc[mt][nt][0] + b0;
            float v1 = acc[mt][nt][1] + b1;
            float v2 = acc[mt][nt][2] + b0;
            float v3 = acc[mt][nt][3] + b1;
            if (MODE == 0) {
                *(float2*)&Cf[(size_t)m0 * Dz + n0]       = make_float2(v0, v1);
                *(float2*)&Cf[(size_t)(m0 + 8) * Dz + n0] = make_float2(v2, v3);
            } else {
                const int h = n0 >> 6, dd = n0 & 63;
                const int b = m0 >> 10, l = m0 & 1023;
                if (blockIdx.z == 2) {
                    float* base = Cf + (((size_t)(b * Hz + h) * Lz) << 6) + dd;
                    *(float2*)(base + ((size_t)l << 6))       = make_float2(v0, v1);
                    *(float2*)(base + ((size_t)(l + 8) << 6)) = make_float2(v2, v3);
                } else {
                    __nv_bfloat16* Ch = (blockIdx.z == 0) ? qh : kh;
                    __nv_bfloat16* Cl = (blockIdx.z == 0) ? ql : kl;
                    const size_t i0 = (((size_t)(b * Hz + h) * Lz + l)     << 6) + dd;
                    const size_t i1 = (((size_t)(b * Hz + h) * Lz + l + 8) << 6) + dd;
                    __nv_bfloat162 lo;
                    __nv_bfloat162 hi = split_hi2(v0, v1, lo);
                    *(__nv_bfloat162*)&Ch[i0] = hi;
                    *(__nv_bfloat162*)&Cl[i0] = lo;
                    hi = split_hi2(v2, v3, lo);
                    *(__nv_bfloat162*)&Ch[i1] = hi;
                    *(__nv_bfloat162*)&Cl[i1] = lo;
                }
            }
        }
    }
}

// ---------------- scores HMMA (streaming stores, term-pass order) -------------------
#define SROW 144
#define SMAT (128 * SROW)
#define SSMEM (4 * SMAT)       // 73728

__global__ __launch_bounds__(256, 2) void scores_hmma(
    const __nv_bfloat16* __restrict__ qh, const __nv_bfloat16* __restrict__ ql,
    const __nv_bfloat16* __restrict__ kh, const __nv_bfloat16* __restrict__ kl,
    const float* __restrict__ bias, float* __restrict__ attn)
{
    extern __shared__ char sm[];
    const uint32_t sbase = smem_u32(sm);

    const int tid  = threadIdx.x;
    const int warp = tid >> 5;
    const int lane = tid & 31;
    const int g = lane >> 2;
    const int t = lane & 3;
    const int wm = (warp >> 2) * 64;
    const int wn = (warp & 3) * 32;

    const int z  = blockIdx.z;
    const int bm = blockIdx.y * 128;
    const int bn = blockIdx.x * 128;

    const size_t zofs = (size_t)z * Lz * HDz;
    const __nv_bfloat16* pqh = qh + zofs + (size_t)bm * HDz;
    const __nv_bfloat16* pql = ql + zofs + (size_t)bm * HDz;
    const __nv_bfloat16* pkh = kh + zofs + (size_t)bn * HDz;
    const __nv_bfloat16* pkl = kl + zofs + (size_t)bn * HDz;

    #pragma unroll
    for (int i = 0; i < 4; i++) {
        const int idx = tid + i * 256;
        const int row = idx >> 3, seg = idx & 7;
        const uint32_t off = row * SROW + seg * 16;
        const size_t go = (size_t)row * HDz + seg * 8;
        cpasync16(sbase + 0 * SMAT + off, pqh + go);
        cpasync16(sbase + 1 * SMAT + off, pql + go);
        cpasync16(sbase + 2 * SMAT + off, pkh + go);
        cpasync16(sbase + 3 * SMAT + off, pkl + go);
    }
    CP_COMMIT();
    CP_WAIT0();
    __syncthreads();

    float acc[4][4][4];
    #pragma unroll
    for (int i = 0; i < 4; i++)
        #pragma unroll
        for (int j = 0; j < 4; j++)
            #pragma unroll
            for (int k = 0; k < 4; k++) acc[i][j][k] = 0.0f;

    const uint32_t sQh = sbase;
    const uint32_t sQl = sbase + 1 * SMAT;
    const uint32_t sKh = sbase + 2 * SMAT;
    const uint32_t sKl = sbase + 3 * SMAT;

    const uint32_t aOff = a_ldsm_off(lane, SROW);
    const uint32_t bOff = b_ldsm_off(lane, SROW);

    #pragma unroll
    for (int kk = 0; kk < 64; kk += 16) {
        const uint32_t kb = kk * 2;

        uint32_t bH[4][2], bL[4][2];
        #pragma unroll
        for (int nt = 0; nt < 4; nt++) {
            const uint32_t ro = (wn + nt * 8) * SROW + kb + bOff;
            ldsm_x2(bH[nt], sKh + ro);
            ldsm_x2(bL[nt], sKl + ro);
        }

        #pragma unroll
        for (int mt = 0; mt < 4; mt++) {
            const uint32_t ro = (wm + mt * 16) * SROW + kb + aOff;
            uint32_t aH[4], aL[4];
            ldsm_x4(aH, sQh + ro);
            ldsm_x4(aL, sQl + ro);

            #pragma unroll
            for (int nt = 0; nt < 4; nt++) hmma(acc[mt][nt], aH, bH[nt]);
            #pragma unroll
            for (int nt = 0; nt < 4; nt++) hmma(acc[mt][nt], aH, bL[nt]);
            #pragma unroll
            for (int nt = 0; nt < 4; nt++) hmma(acc[mt][nt], aL, bH[nt]);
        }
    }

    float* attnZ = attn + (size_t)z * Lz * Lz;
    #pragma unroll
    for (int mt = 0; mt < 4; mt++) {
        const int m0 = bm + wm + mt * 16 + g;
        #pragma unroll
        for (int nt = 0; nt < 4; nt++) {
            const int n0 = bn + wn + nt * 8 + 2 * t;
            const float b0 = bias[n0], b1 = bias[n0 + 1];
            stg_cs_f2(&attnZ[(size_t)m0 * Lz + n0],
                      make_float2(acc[mt][nt][0] * 0.125f + b0, acc[mt][nt][1] * 0.125f + b1));
            stg_cs_f2(&attnZ[(size_t)(m0 + 8) * Lz + n0],
                      make_float2(acc[mt][nt][2] * 0.125f + b0, acc[mt][nt][3] * 0.125f + b1));
        }
    }
}

// ---------------- softmax: no-max, streaming (unchanged R13) --------------------------
__global__ __launch_bounds__(256) void softmax_kernel(float* __restrict__ attn)
{
    const size_t row = blockIdx.x;
    float4* p = reinterpret_cast<float4*>(attn + row * Lz);
    const int tid = threadIdx.x;
    __shared__ float red[8];

    float4 v = ldg_cs_f4(p + tid);
    v.x = __expf(v.x); v.y = __expf(v.y);
    v.z = __expf(v.z); v.w = __expf(v.w);
    float s = v.x + v.y + v.z + v.w;
    #pragma unroll
    for (int o = 16; o > 0; o >>= 1) s += __shfl_xor_sync(0xFFFFFFFFu, s, o);
    if ((tid & 31) == 0) red[tid >> 5] = s;
    __syncthreads();
    s = red[0];
    #pragma unroll
    for (int i = 1; i < 8; i++) s += red[i];

    const float inv = 1.0f / s;
    v.x *= inv; v.y *= inv; v.z *= inv; v.w *= inv;
    stg_cs_f4(p + tid, v);
}

// ---------------- AV HMMA (term-pass order) -------------------------------------------
#define AVF_ROW 144
#define AVF_BYTES (128 * AVF_ROW)
#define AV_HROW 80
#define AV_HBYTES (128 * AV_HROW)
#define AV_VBYTES (64 * AV_HROW)
#define AV_AH_OFF (2 * AVF_BYTES)
#define AV_AL_OFF (AV_AH_OFF + AV_HBYTES)
#define AV_V_OFF  (AV_AL_OFF + AV_HBYTES)
#define AVSMEM (AV_V_OFF + 4 * AV_VBYTES)    // 77824

__global__ __launch_bounds__(256, 2) void av_hmma(
    const float* __restrict__ attn,
    const __nv_bfloat16* __restrict__ vth, const __nv_bfloat16* __restrict__ vtl,
    __nv_bfloat16* __restrict__ Ch, __nv_bfloat16* __restrict__ Cl)
{
    extern __shared__ char sm[];
    const uint32_t sbase = smem_u32(sm);

    const int tid  = threadIdx.x;
    const int warp = tid >> 5;
    const int lane = tid & 31;
    const int g = lane >> 2;
    const int t = lane & 3;
    const int wm = (warp >> 1) * 32;
    const int wn = (warp & 1) * 32;

    const int z  = blockIdx.z;
    const int bm = blockIdx.y * 128;

    const float* pA = attn + (size_t)z * Lz * Lz + (size_t)bm * Lz;
    const __nv_bfloat16* pvh = vth + (size_t)z * HDz * Lz;
    const __nv_bfloat16* pvl = vtl + (size_t)z * HDz * Lz;

    const uint32_t sAh = sbase + AV_AH_OFF;
    const uint32_t sAl = sbase + AV_AL_OFF;
    const uint32_t sV  = sbase + AV_V_OFF;

    const uint32_t aOff = a_ldsm_off(lane, AV_HROW);
    const uint32_t bOff = b_ldsm_off(lane, AV_HROW);

    const int arow = tid >> 3, aseg = tid & 7;
    const int vrow = tid >> 2, vseg = tid & 3;

    auto prefetch = [&](int c, int stage) {
        const uint32_t sa = sbase + stage * AVF_BYTES;
        #pragma unroll
        for (int i = 0; i < 4; i++) {
            const int row = arow + i * 32;
            cpasync16(sa + row * AVF_ROW + aseg * 16,
                      pA + (size_t)row * Lz + c * 32 + aseg * 4);
        }
        const uint32_t sv = sV + stage * (2 * AV_VBYTES);
        cpasync16(sv + vrow * AV_HROW + vseg * 16,
                  pvh + (size_t)vrow * Lz + c * 32 + vseg * 8);
        cpasync16(sv + AV_VBYTES + vrow * AV_HROW + vseg * 16,
                  pvl + (size_t)vrow * Lz + c * 32 + vseg * 8);
    };

    float acc[2][4][4];
    #pragma unroll
    for (int i = 0; i < 2; i++)
        #pragma unroll
        for (int j = 0; j < 4; j++)
            #pragma unroll
            for (int k = 0; k < 4; k++) acc[i][j][k] = 0.0f;

    const int nch = Lz / 32;
    prefetch(0, 0); CP_COMMIT();
    prefetch(1, 1); CP_COMMIT();

    for (int c = 0; c < nch; c++) {
        if (c + 1 < nch) { CP_WAIT1(); } else { CP_WAIT0(); }
        __syncthreads();

        const uint32_t sa = sbase + (c & 1) * AVF_BYTES;
        #pragma unroll
        for (int i = 0; i < 4; i++) {
            const int row = arow + i * 32;
            const float4 v = *(const float4*)(sm + (sa - sbase) + row * AVF_ROW + aseg * 16);
            __nv_bfloat162 lo0, lo1;
            __nv_bfloat162 hi0 = split_hi2(v.x, v.y, lo0);
            __nv_bfloat162 hi1 = split_hi2(v.z, v.w, lo1);
            uint2 h8, l8;
            h8.x = *reinterpret_cast<uint32_t*>(&hi0);
            h8.y = *reinterpret_cast<uint32_t*>(&hi1);
            l8.x = *reinterpret_cast<uint32_t*>(&lo0);
            l8.y = *reinterpret_cast<uint32_t*>(&lo1);
            *(uint2*)(sm + AV_AH_OFF + row * AV_HROW + aseg * 8) = h8;
            *(uint2*)(sm + AV_AL_OFF + row * AV_HROW + aseg * 8) = l8;
        }
        __syncthreads();

        const uint32_t sVh = sV + (c & 1) * (2 * AV_VBYTES);
        const uint32_t sVl = sVh + AV_VBYTES;

        #pragma unroll
        for (int kk = 0; kk < 32; kk += 16) {
            const uint32_t kb = kk * 2;

            uint32_t bH[4][2], bL[4][2];
            #pragma unroll
            for (int nt = 0; nt < 4; nt++) {
                const uint32_t ro = (wn + nt * 8) * AV_HROW + kb + bOff;
                ldsm_x2(bH[nt], sVh + ro);
                ldsm_x2(bL[nt], sVl + ro);
            }

            #pragma unroll
            for (int mt = 0; mt < 2; mt++) {
                const uint32_t ro = (wm + mt * 16) * AV_HROW + kb + aOff;
                uint32_t aH[4], aL[4];
                ldsm_x4(aH, sAh + ro);
                ldsm_x4(aL, sAl + ro);

                #pragma unroll
                for (int nt = 0; nt < 4; nt++) hmma(acc[mt][nt], aH, bH[nt]);
                #pragma unroll
                for (int nt = 0; nt < 4; nt++) hmma(acc[mt][nt], aH, bL[nt]);
                #pragma unroll
                for (int nt = 0; nt < 4; nt++) hmma(acc[mt][nt], aL, bH[nt]);
            }
        }

        __syncthreads();
        if (c + 2 < nch) { prefetch(c + 2, (c & 1)); CP_COMMIT(); }
        else { CP_COMMIT(); }
    }

    const int b = z >> 4, h = z & 15;
    #pragma unroll
    for (int mt = 0; mt < 2; mt++) {
        const int m0 = bm + wm + mt * 16 + g;
        #pragma unroll
        for (int nt = 0; nt < 4; nt++) {
            const int n0 = wn + nt * 8 + 2 * t;
            const size_t i0 = ((size_t)(b * Lz + m0)     << 10) + h * HDz + n0;
            const size_t i1 = ((size_t)(b * Lz + m0 + 8) << 10) + h * HDz + n0;
            __nv_bfloat162 lo;
            __nv_bfloat162 hi = split_hi2(acc[mt][nt][0], acc[mt][nt][1], lo);
            *(__nv_bfloat162*)&Ch[i0] = hi;
            *(__nv_bfloat162*)&Cl[i0] = lo;
            hi = split_hi2(acc[mt][nt][2], acc[mt][nt][3], lo);
            *(__nv_bfloat162*)&Ch[i1] = hi;
            *(__nv_bfloat162*)&Cl[i1] = lo;
        }
    }
}

// ---------------- V transpose + split ------------------------------------------------
__global__ __launch_bounds__(256) void tsplit_v(
    const float* __restrict__ v, __nv_bfloat16* __restrict__ vth,
    __nv_bfloat16* __restrict__ vtl)
{
    __shared__ float tile[32][33];
    const int z  = blockIdx.z;
    const int l0 = blockIdx.x * 32;
    const int d0 = blockIdx.y * 32;
    const int tx = threadIdx.x & 31;
    const int ty = threadIdx.x >> 5;

    const float* src = v + (size_t)z * Lz * HDz;
    #pragma unroll
    for (int j = 0; j < 4; j++)
        tile[ty + j * 8][tx] = src[(size_t)(l0 + ty + j * 8) * HDz + d0 + tx];
    __syncthreads();

    __nv_bfloat16* dh = vth + (size_t)z * HDz * Lz;
    __nv_bfloat16* dl = vtl + (size_t)z * HDz * Lz;
    #pragma unroll
    for (int j = 0; j < 4; j++) {
        const float val = tile[tx][ty + j * 8];
        const __nv_bfloat16 h = __float2bfloat16(val);
        const size_t o = (size_t)(d0 + ty + j * 8) * Lz + l0 + tx;
        dh[o] = h;
        dl[o] = __float2bfloat16(val - __bfloat162float(h));
    }
}

// ---------------- misc small kernels --------------------------------------------------
__global__ __launch_bounds__(256) void split_kernel(
    const float* __restrict__ in, __nv_bfloat16* __restrict__ hi,
    __nv_bfloat16* __restrict__ lo, int n4)
{
    int i = blockIdx.x * (blockDim.x * 4) + threadIdx.x;
    #pragma unroll
    for (int u = 0; u < 4; u++, i += 256) {
        if (i < n4) {
            float4 v = ((const float4*)in)[i];
            __nv_bfloat162* H = (__nv_bfloat162*)hi;
            __nv_bfloat162* L = (__nv_bfloat162*)lo;
            __nv_bfloat162 l2;
            H[i*2+0] = split_hi2(v.x, v.y, l2); L[i*2+0] = l2;
            H[i*2+1] = split_hi2(v.z, v.w, l2); L[i*2+1] = l2;
        }
    }
}

__global__ __launch_bounds__(256) void wsplit4_kernel(
    const float* __restrict__ W0, const float* __restrict__ W1,
    const float* __restrict__ W2, const float* __restrict__ W3,
    __nv_bfloat16* __restrict__ hi, __nv_bfloat16* __restrict__ lo)
{
    const int z = blockIdx.z;
    const float* src = (z == 0) ? W0 : (z == 1) ? W1 : (z == 2) ? W2 : W3;
    const size_t WN = (size_t)Dz * Dz;
    __nv_bfloat162* H = (__nv_bfloat162*)(hi + z * WN);
    __nv_bfloat162* L = (__nv_bfloat162*)(lo + z * WN);
    int i = blockIdx.x * (blockDim.x * 4) + threadIdx.x;
    #pragma unroll
    for (int u = 0; u < 4; u++, i += 256) {
        float4 v = ((const float4*)src)[i];
        __nv_bfloat162 l2;
        H[i*2+0] = split_hi2(v.x, v.y, l2); L[i*2+0] = l2;
        H[i*2+1] = split_hi2(v.z, v.w, l2); L[i*2+1] = l2;
    }
}

__global__ void bias_energy_kernel(const float* __restrict__ field,
                                   const float* __restrict__ strength,
                                   float* __restrict__ bias,
                                   float* __restrict__ e)
{
    if (blockIdx.x == 4) {
        if (threadIdx.x == 0)
            e[0] = (strength[0] * strength[0] + strength[1] * strength[1] +
                    strength[2] * strength[2]) * (1.0f / 3.0f);
        return;
    }
    int m = blockIdx.x * blockDim.x + threadIdx.x;
    if (m < Lz) {
        const float pi = 3.14159265358979323846f;
        float acc = 0.0f;
        #pragma unroll
        for (int i = 0; i < ORDERz; i++) {
            float sig = 1.0f / (1.0f + expf(-field[i * Lz + m]));
            acc += strength[i] * sinf((float)m * (float)(i + 1) * pi / (float)Lz) * sig;
        }
        bias[m] = acc;
    }
}

// ---------------- launch ----------------------------------------------------------------
extern "C" void kernel_launch(void* const* d_in, const int* in_sizes, int n_in,
                              void* d_out, int out_size)
{
    const float* x  = (const float*)d_in[0];
    const float* Wq = (const float*)d_in[1];
    const float* bq = (const float*)d_in[2];
    const float* Wk = (const float*)d_in[3];
    const float* bk = (const float*)d_in[4];
    const float* Wv = (const float*)d_in[5];
    const float* bv = (const float*)d_in[6];
    const float* Wo = (const float*)d_in[7];
    const float* bo = (const float*)d_in[8];
    const float* tf = (const float*)d_in[9];
    const float* ts = (const float*)d_in[10];

    float* out    = (float*)d_out;
    float* attn   = out + (size_t)Bz * Lz * Dz;
    float* energy = attn + (size_t)ZN * Lz * Lz;

    float *gv, *gbias;
    cudaGetSymbolAddress((void**)&gv,    g_v);
    cudaGetSymbolAddress((void**)&gbias, g_bias);

    __nv_bfloat16 *xh, *xl, *wh, *wl, *qh, *ql, *kh, *kl, *vth, *vtl, *ch, *cl;
    cudaGetSymbolAddress((void**)&xh,  g_xh);
    cudaGetSymbolAddress((void**)&xl,  g_xl);
    cudaGetSymbolAddress((void**)&wh,  g_wh);
    cudaGetSymbolAddress((void**)&wl,  g_wl);
    cudaGetSymbolAddress((void**)&qh,  g_qh);
    cudaGetSymbolAddress((void**)&ql,  g_ql);
    cudaGetSymbolAddress((void**)&kh,  g_kh);
    cudaGetSymbolAddress((void**)&kl,  g_kl);
    cudaGetSymbolAddress((void**)&vth, g_vth);
    cudaGetSymbolAddress((void**)&vtl, g_vtl);
    cudaGetSymbolAddress((void**)&ch,  g_ch);
    cudaGetSymbolAddress((void**)&cl,  g_cl);

    cudaFuncSetAttribute(gemm512<0>,  cudaFuncAttributeMaxDynamicSharedMemorySize, GSMEM);
    cudaFuncSetAttribute(gemm512<1>,  cudaFuncAttributeMaxDynamicSharedMemorySize, GSMEM);
    cudaFuncSetAttribute(scores_hmma, cudaFuncAttributeMaxDynamicSharedMemorySize, SSMEM);
    cudaFuncSetAttribute(av_hmma,     cudaFuncAttributeMaxDynamicSharedMemorySize, AVSMEM);

    bias_energy_kernel<<<5, 256>>>(tf, ts, gbias, energy);

    const size_t WN = (size_t)Dz * Dz;
    split_kernel<<<(Mz*Dz/4 + 1023)/1024, 256>>>(x, xh, xl, Mz*Dz/4);
    wsplit4_kernel<<<dim3((WN/4)/1024, 1, 4), 256>>>(Wq, Wk, Wv, Wo, wh, wl);

    gemm512<1><<<dim3(Dz/256, Mz/128, 3), 512, GSMEM>>>(
        xh, xl, wh, wl, bq, bk, bv, qh, ql, kh, kl, gv);

    tsplit_v<<<dim3(Lz/32, HDz/32, ZN), 256>>>(gv, vth, vtl);

    scores_hmma<<<dim3(8, 8, ZN), 256, SSMEM>>>(qh, ql, kh, kl, gbias, attn);

    softmax_kernel<<<ZN * Lz, 256>>>(attn);

    av_hmma<<<dim3(1, Lz/128, ZN), 256, AVSMEM>>>(attn, vth, vtl, ch, cl);

    gemm512<0><<<dim3(Dz/256, Mz/128), 512, GSMEM>>>(
        ch, cl, wh + 3*WN, wl + 3*WN, bo, nullptr, nullptr,
        nullptr, nullptr, nullptr, nullptr, out);
}

// round 16
// speedup vs baseline: 1.0957x; 1.0818x over previous
#include <cuda_runtime.h>
#include <cuda_bf16.h>
#include <math.h>
#include <stdint.h>

#define Bz   4
#define Lz   1024
#define Dz   1024
#define Hz   16
#define HDz  64
#define Mz   (Bz*Lz)          // 4096
#define ORDERz 3
#define ZN   (Bz*Hz)          // 64

// ---------------- scratch (__device__ globals) ----------------------------------
__device__ __align__(16) float g_v[Mz*Dz];     // (B,H,L,hd) fp32
__device__ __align__(16) float g_bias[Lz];
__device__ __align__(16) float g_rowsum[(size_t)ZN*Lz*8];   // per-CTA partial row sums

__device__ __align__(16) __nv_bfloat16 g_xh[Mz*Dz], g_xl[Mz*Dz];
__device__ __align__(16) __nv_bfloat16 g_wh[4][Dz*Dz], g_wl[4][Dz*Dz]; // q,k,v,o
__device__ __align__(16) __nv_bfloat16 g_qh[Mz*Dz], g_ql[Mz*Dz];       // (B,H,L,hd)
__device__ __align__(16) __nv_bfloat16 g_kh[Mz*Dz], g_kl[Mz*Dz];       // (B,H,L,hd)
__device__ __align__(16) __nv_bfloat16 g_vth[Mz*Dz], g_vtl[Mz*Dz];     // (B,H,hd,L)
__device__ __align__(16) __nv_bfloat16 g_ch[Mz*Dz], g_cl[Mz*Dz];       // ctx (B,L,D)

// ---------------- PTX helpers ----------------------------------------------------
__device__ __forceinline__ uint32_t smem_u32(const void* p) {
    uint32_t a;
    asm("{ .reg .u64 t; cvta.to.shared.u64 t, %1; cvt.u32.u64 %0, t; }" : "=r"(a) : "l"(p));
    return a;
}
__device__ __forceinline__ void cpasync16(uint32_t s, const void* g) {
    asm volatile("cp.async.cg.shared.global [%0], [%1], 16;" :: "r"(s), "l"(g));
}
#define CP_COMMIT()  asm volatile("cp.async.commit_group;" ::: "memory")
#define CP_WAIT2()   asm volatile("cp.async.wait_group 2;" ::: "memory")
#define CP_WAIT1()   asm volatile("cp.async.wait_group 1;" ::: "memory")
#define CP_WAIT0()   asm volatile("cp.async.wait_group 0;" ::: "memory")

__device__ __forceinline__ void stg_cs_f2(float* p, float2 v) {
    asm volatile("st.global.cs.v2.f32 [%0], {%1, %2};" :: "l"(p), "f"(v.x), "f"(v.y) : "memory");
}
__device__ __forceinline__ void stg_cs_f4(float* p, float4 v) {
    asm volatile("st.global.cs.v4.f32 [%0], {%1,%2,%3,%4};"
        :: "l"(p), "f"(v.x), "f"(v.y), "f"(v.z), "f"(v.w) : "memory");
}

__device__ __forceinline__ void hmma(float* d, const uint32_t* a, const uint32_t* b) {
    asm volatile(
        "mma.sync.aligned.m16n8k16.row.col.f32.bf16.bf16.f32 "
        "{%0,%1,%2,%3}, {%4,%5,%6,%7}, {%8,%9}, {%0,%1,%2,%3};"
        : "+f"(d[0]), "+f"(d[1]), "+f"(d[2]), "+f"(d[3])
        : "r"(a[0]), "r"(a[1]), "r"(a[2]), "r"(a[3]), "r"(b[0]), "r"(b[1]));
}
__device__ __forceinline__ void ldsm_x4(uint32_t* r, uint32_t saddr) {
    asm volatile("ldmatrix.sync.aligned.m8n8.x4.shared.b16 {%0,%1,%2,%3}, [%4];"
        : "=r"(r[0]), "=r"(r[1]), "=r"(r[2]), "=r"(r[3]) : "r"(saddr));
}
__device__ __forceinline__ void ldsm_x2(uint32_t* r, uint32_t saddr) {
    asm volatile("ldmatrix.sync.aligned.m8n8.x2.shared.b16 {%0,%1}, [%2];"
        : "=r"(r[0]), "=r"(r[1]) : "r"(saddr));
}

__device__ __forceinline__ __nv_bfloat162 split_hi2(float x, float y,
                                                    __nv_bfloat162& lo2) {
    __nv_bfloat16 hx = __float2bfloat16(x);
    __nv_bfloat16 hy = __float2bfloat16(y);
    lo2 = __nv_bfloat162(__float2bfloat16(x - __bfloat162float(hx)),
                         __float2bfloat16(y - __bfloat162float(hy)));
    return __nv_bfloat162(hx, hy);
}

__device__ __forceinline__ uint32_t a_ldsm_off(int lane, int RS) {
    return (uint32_t)((lane & 7) * RS + ((lane >> 3) & 1) * 8 * RS + ((lane >> 4) & 1) * 16);
}
__device__ __forceinline__ uint32_t b_ldsm_off(int lane, int RS) {
    const int l = lane & 15;
    return (uint32_t)((l & 7) * RS + ((l >> 3) & 1) * 16);
}

// ---------------- 512-thread, 128x256-tile, 3-stage HMMA GEMM ----------------------
#define KC 32
#define ROWB 80
#define G_AM (128 * ROWB)
#define G_BM (256 * ROWB)
#define G_STAGE (2 * G_AM + 2 * G_BM)    // 61440
#define GSMEM (3 * G_STAGE)              // 184320

template<int MODE>
__global__ __launch_bounds__(512, 1) void gemm512(
    const __nv_bfloat16* __restrict__ Ah, const __nv_bfloat16* __restrict__ Al,
    const __nv_bfloat16* __restrict__ whBase, const __nv_bfloat16* __restrict__ wlBase,
    const float* __restrict__ bq, const float* __restrict__ bk, const float* __restrict__ bv,
    __nv_bfloat16* __restrict__ qh, __nv_bfloat16* __restrict__ ql,
    __nv_bfloat16* __restrict__ kh, __nv_bfloat16* __restrict__ kl,
    float* __restrict__ Cf)
{
    extern __shared__ char sm[];
    const uint32_t sbase = smem_u32(sm);

    const int zz = (MODE == 1) ? blockIdx.z : 0;     // MODE 0: base pre-offset to Wo
    const size_t WN = (size_t)Dz * Dz;
    const __nv_bfloat16* Bh = whBase + (size_t)zz * WN;
    const __nv_bfloat16* Bl = wlBase + (size_t)zz * WN;
    const float* bias = (MODE == 0) ? bq : (blockIdx.z == 0) ? bq : (blockIdx.z == 1) ? bk : bv;

    const int K = Dz;
    const int tid  = threadIdx.x;
    const int warp = tid >> 5;
    const int lane = tid & 31;
    const int g = lane >> 2;
    const int t = lane & 3;
    const int wm = (warp >> 3) * 64;
    const int wn = (warp & 7) * 32;

    const int bm = blockIdx.y * 128;
    const int bn = blockIdx.x * 256;

    const __nv_bfloat16* tAh = Ah + (size_t)bm * K;
    const __nv_bfloat16* tAl = Al + (size_t)bm * K;
    const __nv_bfloat16* tBh = Bh + (size_t)bn * K;
    const __nv_bfloat16* tBl = Bl + (size_t)bn * K;

    const int ar = tid >> 2, as = tid & 3;

    const uint32_t aOff = a_ldsm_off(lane, ROWB);
    const uint32_t bOff = b_ldsm_off(lane, ROWB);

    auto prefetch = [&](int c, int stage) {
        const uint32_t sb = sbase + stage * G_STAGE;
        const int kb = c * KC;
        {
            const size_t go = (size_t)ar * K + kb + as * 8;
            const uint32_t so = ar * ROWB + as * 16;
            cpasync16(sb + so, tAh + go);
            cpasync16(sb + G_AM + so, tAl + go);
        }
        #pragma unroll
        for (int i = 0; i < 2; i++) {
            const int idx = tid + i * 512;
            const int row = idx >> 2, seg = idx & 3;
            const size_t go = (size_t)row * K + kb + seg * 8;
            const uint32_t so = row * ROWB + seg * 16;
            cpasync16(sb + 2 * G_AM + so, tBh + go);
            cpasync16(sb + 2 * G_AM + G_BM + so, tBl + go);
        }
    };

    float acc[4][4][4];
    #pragma unroll
    for (int i = 0; i < 4; i++)
        #pragma unroll
        for (int j = 0; j < 4; j++)
            #pragma unroll
            for (int k = 0; k < 4; k++) acc[i][j][k] = 0.0f;

    const int nch = K / KC;   // 32
    prefetch(0, 0); CP_COMMIT();
    prefetch(1, 1); CP_COMMIT();
    prefetch(2, 2); CP_COMMIT();

    for (int c = 0; c < nch; c++) {
        if (c + 2 < nch) { CP_WAIT2(); }
        else if (c + 1 < nch) { CP_WAIT1(); }
        else { CP_WAIT0(); }
        __syncthreads();

        const int st = c % 3;
        const uint32_t sb  = sbase + st * G_STAGE;
        const uint32_t sAh = sb;
        const uint32_t sAl = sb + G_AM;
        const uint32_t sBh = sb + 2 * G_AM;
        const uint32_t sBl = sb + 2 * G_AM + G_BM;

        #pragma unroll
        for (int kk = 0; kk < KC; kk += 16) {
            const uint32_t kb = kk * 2;

            uint32_t bH[4][2], bL[4][2];
            #pragma unroll
            for (int nt = 0; nt < 4; nt++) {
                const uint32_t ro = (wn + nt * 8) * ROWB + kb + bOff;
                ldsm_x2(bH[nt], sBh + ro);
                ldsm_x2(bL[nt], sBl + ro);
            }

            #pragma unroll
            for (int mt = 0; mt < 4; mt++) {
                const uint32_t ro = (wm + mt * 16) * ROWB + kb + aOff;
                uint32_t aH[4], aL[4];
                ldsm_x4(aH, sAh + ro);
                ldsm_x4(aL, sAl + ro);

                #pragma unroll
                for (int nt = 0; nt < 4; nt++) hmma(acc[mt][nt], aH, bH[nt]);
                #pragma unroll
                for (int nt = 0; nt < 4; nt++) hmma(acc[mt][nt], aH, bL[nt]);
                #pragma unroll
                for (int nt = 0; nt < 4; nt++) hmma(acc[mt][nt], aL, bH[nt]);
            }
        }

        __syncthreads();
        if (c + 3 < nch) { prefetch(c + 3, st); }
        CP_COMMIT();
    }

    #pragma unroll
    for (int mt = 0; mt < 4; mt++) {
        const int m0 = bm + wm + mt * 16 + g;
        #pragma unroll
        for (int nt = 0; nt < 4; nt++) {
            const int n0 = bn + wn + nt * 8 + 2 * t;
            const float b0 = bias[n0], b1 = bias[n0 + 1];
            float v0 = acc[mt][nt][0] + b0;
            float v1 = acc[mt][nt][1] + b1;
            float v2 = acc[mt][nt][2] + b0;
            float v3 = acc[mt][nt][3] + b1;
            if (MODE == 0) {
                *(float2*)&Cf[(size_t)m0 * Dz + n0]       = make_float2(v0, v1);
                *(float2*)&Cf[(size_t)(m0 + 8) * Dz + n0] = make_float2(v2, v3);
            } else {
                const int h = n0 >> 6, dd = n0 & 63;
                const int b = m0 >> 10, l = m0 & 1023;
                if (blockIdx.z == 2) {
                    float* base = Cf + (((size_t)(b * Hz + h) * Lz) << 6) + dd;
                    *(float2*)(base + ((size_t)l << 6))       = make_float2(v0, v1);
                    *(float2*)(base + ((size_t)(l + 8) << 6)) = make_float2(v2, v3);
                } else {
                    __nv_bfloat16* Ch = (blockIdx.z == 0) ? qh : kh;
                    __nv_bfloat16* Cl = (blockIdx.z == 0) ? ql : kl;
                    const size_t i0 = (((size_t)(b * Hz + h) * Lz + l)     << 6) + dd;
                    const size_t i1 = (((size_t)(b * Hz + h) * Lz + l + 8) << 6) + dd;
                    __nv_bfloat162 lo;
                    __nv_bfloat162 hi = split_hi2(v0, v1, lo);
                    *(__nv_bfloat162*)&Ch[i0] = hi;
                    *(__nv_bfloat162*)&Cl[i0] = lo;
                    hi = split_hi2(v2, v3, lo);
                    *(__nv_bfloat162*)&Ch[i1] = hi;
                    *(__nv_bfloat162*)&Cl[i1] = lo;
                }
            }
        }
    }
}

// ---------------- scores HMMA: writes e=exp(score+bias), partial row sums ----------
#define SROW 144
#define SMAT (128 * SROW)
#define SSMEM (4 * SMAT)       // 73728 dynamic (+512 static)

__global__ __launch_bounds__(256, 2) void scores_hmma(
    const __nv_bfloat16* __restrict__ qh, const __nv_bfloat16* __restrict__ ql,
    const __nv_bfloat16* __restrict__ kh, const __nv_bfloat16* __restrict__ kl,
    const float* __restrict__ bias, float* __restrict__ attn,
    float* __restrict__ rowsum)
{
    extern __shared__ char sm[];
    const uint32_t sbase = smem_u32(sm);
    __shared__ float sums[128];

    const int tid  = threadIdx.x;
    const int warp = tid >> 5;
    const int lane = tid & 31;
    const int g = lane >> 2;
    const int t = lane & 3;
    const int wm = (warp >> 2) * 64;
    const int wn = (warp & 3) * 32;

    const int z  = blockIdx.z;
    const int bm = blockIdx.y * 128;
    const int bn = blockIdx.x * 128;

    const size_t zofs = (size_t)z * Lz * HDz;
    const __nv_bfloat16* pqh = qh + zofs + (size_t)bm * HDz;
    const __nv_bfloat16* pql = ql + zofs + (size_t)bm * HDz;
    const __nv_bfloat16* pkh = kh + zofs + (size_t)bn * HDz;
    const __nv_bfloat16* pkl = kl + zofs + (size_t)bn * HDz;

    #pragma unroll
    for (int i = 0; i < 4; i++) {
        const int idx = tid + i * 256;
        const int row = idx >> 3, seg = idx & 7;
        const uint32_t off = row * SROW + seg * 16;
        const size_t go = (size_t)row * HDz + seg * 8;
        cpasync16(sbase + 0 * SMAT + off, pqh + go);
        cpasync16(sbase + 1 * SMAT + off, pql + go);
        cpasync16(sbase + 2 * SMAT + off, pkh + go);
        cpasync16(sbase + 3 * SMAT + off, pkl + go);
    }
    if (tid < 128) sums[tid] = 0.0f;
    CP_COMMIT();
    CP_WAIT0();
    __syncthreads();

    float acc[4][4][4];
    #pragma unroll
    for (int i = 0; i < 4; i++)
        #pragma unroll
        for (int j = 0; j < 4; j++)
            #pragma unroll
            for (int k = 0; k < 4; k++) acc[i][j][k] = 0.0f;

    const uint32_t sQh = sbase;
    const uint32_t sQl = sbase + 1 * SMAT;
    const uint32_t sKh = sbase + 2 * SMAT;
    const uint32_t sKl = sbase + 3 * SMAT;

    const uint32_t aOff = a_ldsm_off(lane, SROW);
    const uint32_t bOff = b_ldsm_off(lane, SROW);

    #pragma unroll
    for (int kk = 0; kk < 64; kk += 16) {
        const uint32_t kb = kk * 2;

        uint32_t bH[4][2], bL[4][2];
        #pragma unroll
        for (int nt = 0; nt < 4; nt++) {
            const uint32_t ro = (wn + nt * 8) * SROW + kb + bOff;
            ldsm_x2(bH[nt], sKh + ro);
            ldsm_x2(bL[nt], sKl + ro);
        }

        #pragma unroll
        for (int mt = 0; mt < 4; mt++) {
            const uint32_t ro = (wm + mt * 16) * SROW + kb + aOff;
            uint32_t aH[4], aL[4];
            ldsm_x4(aH, sQh + ro);
            ldsm_x4(aL, sQl + ro);

            #pragma unroll
            for (int nt = 0; nt < 4; nt++) hmma(acc[mt][nt], aH, bH[nt]);
            #pragma unroll
            for (int nt = 0; nt < 4; nt++) hmma(acc[mt][nt], aH, bL[nt]);
            #pragma unroll
            for (int nt = 0; nt < 4; nt++) hmma(acc[mt][nt], aL, bH[nt]);
        }
    }

    // epilogue: e = exp(score/8 + bias); write e, accumulate partial row sums.
    float* attnZ = attn + (size_t)z * Lz * Lz;
    float pr0[4], pr1[4];
    #pragma unroll
    for (int mt = 0; mt < 4; mt++) { pr0[mt] = 0.0f; pr1[mt] = 0.0f; }

    #pragma unroll
    for (int mt = 0; mt < 4; mt++) {
        const int m0 = bm + wm + mt * 16 + g;
        #pragma unroll
        for (int nt = 0; nt < 4; nt++) {
            const int n0 = bn + wn + nt * 8 + 2 * t;
            const float b0 = bias[n0], b1 = bias[n0 + 1];
            const float e0 = __expf(acc[mt][nt][0] * 0.125f + b0);
            const float e1 = __expf(acc[mt][nt][1] * 0.125f + b1);
            const float e2 = __expf(acc[mt][nt][2] * 0.125f + b0);
            const float e3 = __expf(acc[mt][nt][3] * 0.125f + b1);
            stg_cs_f2(&attnZ[(size_t)m0 * Lz + n0],       make_float2(e0, e1));
            stg_cs_f2(&attnZ[(size_t)(m0 + 8) * Lz + n0], make_float2(e2, e3));
            pr0[mt] += e0 + e1;
            pr1[mt] += e2 + e3;
        }
    }
    // reduce over quad (t = 0..3 share the same row)
    #pragma unroll
    for (int o = 1; o <= 2; o <<= 1) {
        #pragma unroll
        for (int mt = 0; mt < 4; mt++) {
            pr0[mt] += __shfl_xor_sync(0xFFFFFFFFu, pr0[mt], o);
            pr1[mt] += __shfl_xor_sync(0xFFFFFFFFu, pr1[mt], o);
        }
    }
    if (t == 0) {
        #pragma unroll
        for (int mt = 0; mt < 4; mt++) {
            atomicAdd(&sums[wm + mt * 16 + g],     pr0[mt]);
            atomicAdd(&sums[wm + mt * 16 + g + 8], pr1[mt]);
        }
    }
    __syncthreads();
    if (tid < 128)
        rowsum[((size_t)z * Lz + bm + tid) * 8 + (bn >> 7)] = sums[tid];
}

// ---------------- AV HMMA: normalizes raw e, writes attn output, does AV ------------
#define AVF_ROW 144
#define AVF_BYTES (128 * AVF_ROW)
#define AV_HROW 80
#define AV_HBYTES (128 * AV_HROW)
#define AV_VBYTES (64 * AV_HROW)
#define AV_AH_OFF (2 * AVF_BYTES)
#define AV_AL_OFF (AV_AH_OFF + AV_HBYTES)
#define AV_V_OFF  (AV_AL_OFF + AV_HBYTES)
#define AVSMEM (AV_V_OFF + 4 * AV_VBYTES)    // 77824 dynamic (+512 static)

__global__ __launch_bounds__(256, 2) void av_hmma(
    float* __restrict__ attn, const float* __restrict__ rowsum,
    const __nv_bfloat16* __restrict__ vth, const __nv_bfloat16* __restrict__ vtl,
    __nv_bfloat16* __restrict__ Ch, __nv_bfloat16* __restrict__ Cl)
{
    extern __shared__ char sm[];
    const uint32_t sbase = smem_u32(sm);
    __shared__ float inv_s[128];

    const int tid  = threadIdx.x;
    const int warp = tid >> 5;
    const int lane = tid & 31;
    const int g = lane >> 2;
    const int t = lane & 3;
    const int wm = (warp >> 1) * 32;
    const int wn = (warp & 1) * 32;

    const int z  = blockIdx.z;
    const int bm = blockIdx.y * 128;

    float* pA = attn + (size_t)z * Lz * Lz + (size_t)bm * Lz;
    const __nv_bfloat16* pvh = vth + (size_t)z * HDz * Lz;
    const __nv_bfloat16* pvl = vtl + (size_t)z * HDz * Lz;

    const uint32_t sAh = sbase + AV_AH_OFF;
    const uint32_t sAl = sbase + AV_AL_OFF;
    const uint32_t sV  = sbase + AV_V_OFF;

    const uint32_t aOff = a_ldsm_off(lane, AV_HROW);
    const uint32_t bOff = b_ldsm_off(lane, AV_HROW);

    const int arow = tid >> 3, aseg = tid & 7;
    const int vrow = tid >> 2, vseg = tid & 3;

    // row sums -> 1/s in smem (visible after first __syncthreads in loop)
    if (tid < 128) {
        const float* rs = rowsum + ((size_t)z * Lz + bm + tid) * 8;
        float s = (rs[0] + rs[1]) + (rs[2] + rs[3]) + (rs[4] + rs[5]) + (rs[6] + rs[7]);
        inv_s[tid] = 1.0f / s;
    }

    auto prefetch = [&](int c, int stage) {
        const uint32_t sa = sbase + stage * AVF_BYTES;
        #pragma unroll
        for (int i = 0; i < 4; i++) {
            const int row = arow + i * 32;
            cpasync16(sa + row * AVF_ROW + aseg * 16,
                      pA + (size_t)row * Lz + c * 32 + aseg * 4);
        }
        const uint32_t sv = sV + stage * (2 * AV_VBYTES);
        cpasync16(sv + vrow * AV_HROW + vseg * 16,
                  pvh + (size_t)vrow * Lz + c * 32 + vseg * 8);
        cpasync16(sv + AV_VBYTES + vrow * AV_HROW + vseg * 16,
                  pvl + (size_t)vrow * Lz + c * 32 + vseg * 8);
    };

    float acc[2][4][4];
    #pragma unroll
    for (int i = 0; i < 2; i++)
        #pragma unroll
        for (int j = 0; j < 4; j++)
            #pragma unroll
            for (int k = 0; k < 4; k++) acc[i][j][k] = 0.0f;

    const int nch = Lz / 32;
    prefetch(0, 0); CP_COMMIT();
    prefetch(1, 1); CP_COMMIT();

    for (int c = 0; c < nch; c++) {
        if (c + 1 < nch) { CP_WAIT1(); } else { CP_WAIT0(); }
        __syncthreads();

        // convert raw e -> normalized; write attn output; stage bf16 hi/lo for HMMA
        const uint32_t sa = sbase + (c & 1) * AVF_BYTES;
        #pragma unroll
        for (int i = 0; i < 4; i++) {
            const int row = arow + i * 32;
            const float4 v = *(const float4*)(sm + (sa - sbase) + row * AVF_ROW + aseg * 16);
            const float is = inv_s[row];
            const float4 w = make_float4(v.x * is, v.y * is, v.z * is, v.w * is);
            stg_cs_f4(pA + (size_t)row * Lz + c * 32 + aseg * 4, w);
            __nv_bfloat162 lo0, lo1;
            __nv_bfloat162 hi0 = split_hi2(w.x, w.y, lo0);
            __nv_bfloat162 hi1 = split_hi2(w.z, w.w, lo1);
            uint2 h8, l8;
            h8.x = *reinterpret_cast<uint32_t*>(&hi0);
            h8.y = *reinterpret_cast<uint32_t*>(&hi1);
            l8.x = *reinterpret_cast<uint32_t*>(&lo0);
            l8.y = *reinterpret_cast<uint32_t*>(&lo1);
            *(uint2*)(sm + AV_AH_OFF + row * AV_HROW + aseg * 8) = h8;
            *(uint2*)(sm + AV_AL_OFF + row * AV_HROW + aseg * 8) = l8;
        }
        __syncthreads();

        const uint32_t sVh = sV + (c & 1) * (2 * AV_VBYTES);
        const uint32_t sVl = sVh + AV_VBYTES;

        #pragma unroll
        for (int kk = 0; kk < 32; kk += 16) {
            const uint32_t kb = kk * 2;

            uint32_t bH[4][2], bL[4][2];
            #pragma unroll
            for (int nt = 0; nt < 4; nt++) {
                const uint32_t ro = (wn + nt * 8) * AV_HROW + kb + bOff;
                ldsm_x2(bH[nt], sVh + ro);
                ldsm_x2(bL[nt], sVl + ro);
            }

            #pragma unroll
            for (int mt = 0; mt < 2; mt++) {
                const uint32_t ro = (wm + mt * 16) * AV_HROW + kb + aOff;
                uint32_t aH[4], aL[4];
                ldsm_x4(aH, sAh + ro);
                ldsm_x4(aL, sAl + ro);

                #pragma unroll
                for (int nt = 0; nt < 4; nt++) hmma(acc[mt][nt], aH, bH[nt]);
                #pragma unroll
                for (int nt = 0; nt < 4; nt++) hmma(acc[mt][nt], aH, bL[nt]);
                #pragma unroll
                for (int nt = 0; nt < 4; nt++) hmma(acc[mt][nt], aL, bH[nt]);
            }
        }

        __syncthreads();
        if (c + 2 < nch) { prefetch(c + 2, (c & 1)); CP_COMMIT(); }
        else { CP_COMMIT(); }
    }

    const int b = z >> 4, h = z & 15;
    #pragma unroll
    for (int mt = 0; mt < 2; mt++) {
        const int m0 = bm + wm + mt * 16 + g;
        #pragma unroll
        for (int nt = 0; nt < 4; nt++) {
            const int n0 = wn + nt * 8 + 2 * t;
            const size_t i0 = ((size_t)(b * Lz + m0)     << 10) + h * HDz + n0;
            const size_t i1 = ((size_t)(b * Lz + m0 + 8) << 10) + h * HDz + n0;
            __nv_bfloat162 lo;
            __nv_bfloat162 hi = split_hi2(acc[mt][nt][0], acc[mt][nt][1], lo);
            *(__nv_bfloat162*)&Ch[i0] = hi;
            *(__nv_bfloat162*)&Cl[i0] = lo;
            hi = split_hi2(acc[mt][nt][2], acc[mt][nt][3], lo);
            *(__nv_bfloat162*)&Ch[i1] = hi;
            *(__nv_bfloat162*)&Cl[i1] = lo;
        }
    }
}

// ---------------- V transpose + split ------------------------------------------------
__global__ __launch_bounds__(256) void tsplit_v(
    const float* __restrict__ v, __nv_bfloat16* __restrict__ vth,
    __nv_bfloat16* __restrict__ vtl)
{
    __shared__ float tile[32][33];
    const int z  = blockIdx.z;
    const int l0 = blockIdx.x * 32;
    const int d0 = blockIdx.y * 32;
    const int tx = threadIdx.x & 31;
    const int ty = threadIdx.x >> 5;

    const float* src = v + (size_t)z * Lz * HDz;
    #pragma unroll
    for (int j = 0; j < 4; j++)
        tile[ty + j * 8][tx] = src[(size_t)(l0 + ty + j * 8) * HDz + d0 + tx];
    __syncthreads();

    __nv_bfloat16* dh = vth + (size_t)z * HDz * Lz;
    __nv_bfloat16* dl = vtl + (size_t)z * HDz * Lz;
    #pragma unroll
    for (int j = 0; j < 4; j++) {
        const float val = tile[tx][ty + j * 8];
        const __nv_bfloat16 h = __float2bfloat16(val);
        const size_t o = (size_t)(d0 + ty + j * 8) * Lz + l0 + tx;
        dh[o] = h;
        dl[o] = __float2bfloat16(val - __bfloat162float(h));
    }
}

// ---------------- misc small kernels --------------------------------------------------
__global__ __launch_bounds__(256) void split_kernel(
    const float* __restrict__ in, __nv_bfloat16* __restrict__ hi,
    __nv_bfloat16* __restrict__ lo, int n4)
{
    int i = blockIdx.x * (blockDim.x * 4) + threadIdx.x;
    #pragma unroll
    for (int u = 0; u < 4; u++, i += 256) {
        if (i < n4) {
            float4 v = ((const float4*)in)[i];
            __nv_bfloat162* H = (__nv_bfloat162*)hi;
            __nv_bfloat162* L = (__nv_bfloat162*)lo;
            __nv_bfloat162 l2;
            H[i*2+0] = split_hi2(v.x, v.y, l2); L[i*2+0] = l2;
            H[i*2+1] = split_hi2(v.z, v.w, l2); L[i*2+1] = l2;
        }
    }
}

__global__ __launch_bounds__(256) void wsplit4_kernel(
    const float* __restrict__ W0, const float* __restrict__ W1,
    const float* __restrict__ W2, const float* __restrict__ W3,
    __nv_bfloat16* __restrict__ hi, __nv_bfloat16* __restrict__ lo)
{
    const int z = blockIdx.z;
    const float* src = (z == 0) ? W0 : (z == 1) ? W1 : (z == 2) ? W2 : W3;
    const size_t WN = (size_t)Dz * Dz;
    __nv_bfloat162* H = (__nv_bfloat162*)(hi + z * WN);
    __nv_bfloat162* L = (__nv_bfloat162*)(lo + z * WN);
    int i = blockIdx.x * (blockDim.x * 4) + threadIdx.x;
    #pragma unroll
    for (int u = 0; u < 4; u++, i += 256) {
        float4 v = ((const float4*)src)[i];
        __nv_bfloat162 l2;
        H[i*2+0] = split_hi2(v.x, v.y, l2); L[i*2+0] = l2;
        H[i*2+1] = split_hi2(v.z, v.w, l2); L[i*2+1] = l2;
    }
}

__global__ void bias_energy_kernel(const float* __restrict__ field,
                                   const float* __restrict__ strength,
                                   float* __restrict__ bias,
                                   float* __restrict__ e)
{
    if (blockIdx.x == 4) {
        if (threadIdx.x == 0)
            e[0] = (strength[0] * strength[0] + strength[1] * strength[1] +
                    strength[2] * strength[2]) * (1.0f / 3.0f);
        return;
    }
    int m = blockIdx.x * blockDim.x + threadIdx.x;
    if (m < Lz) {
        const float pi = 3.14159265358979323846f;
        float acc = 0.0f;
        #pragma unroll
        for (int i = 0; i < ORDERz; i++) {
            float sig = 1.0f / (1.0f + expf(-field[i * Lz + m]));
            acc += strength[i] * sinf((float)m * (float)(i + 1) * pi / (float)Lz) * sig;
        }
        bias[m] = acc;
    }
}

// ---------------- launch ----------------------------------------------------------------
extern "C" void kernel_launch(void* const* d_in, const int* in_sizes, int n_in,
                              void* d_out, int out_size)
{
    const float* x  = (const float*)d_in[0];
    const float* Wq = (const float*)d_in[1];
    const float* bq = (const float*)d_in[2];
    const float* Wk = (const float*)d_in[3];
    const float* bk = (const float*)d_in[4];
    const float* Wv = (const float*)d_in[5];
    const float* bv = (const float*)d_in[6];
    const float* Wo = (const float*)d_in[7];
    const float* bo = (const float*)d_in[8];
    const float* tf = (const float*)d_in[9];
    const float* ts = (const float*)d_in[10];

    float* out    = (float*)d_out;
    float* attn   = out + (size_t)Bz * Lz * Dz;
    float* energy = attn + (size_t)ZN * Lz * Lz;

    float *gv, *gbias, *grs;
    cudaGetSymbolAddress((void**)&gv,    g_v);
    cudaGetSymbolAddress((void**)&gbias, g_bias);
    cudaGetSymbolAddress((void**)&grs,   g_rowsum);

    __nv_bfloat16 *xh, *xl, *wh, *wl, *qh, *ql, *kh, *kl, *vth, *vtl, *ch, *cl;
    cudaGetSymbolAddress((void**)&xh,  g_xh);
    cudaGetSymbolAddress((void**)&xl,  g_xl);
    cudaGetSymbolAddress((void**)&wh,  g_wh);
    cudaGetSymbolAddress((void**)&wl,  g_wl);
    cudaGetSymbolAddress((void**)&qh,  g_qh);
    cudaGetSymbolAddress((void**)&ql,  g_ql);
    cudaGetSymbolAddress((void**)&kh,  g_kh);
    cudaGetSymbolAddress((void**)&kl,  g_kl);
    cudaGetSymbolAddress((void**)&vth, g_vth);
    cudaGetSymbolAddress((void**)&vtl, g_vtl);
    cudaGetSymbolAddress((void**)&ch,  g_ch);
    cudaGetSymbolAddress((void**)&cl,  g_cl);

    cudaFuncSetAttribute(gemm512<0>,  cudaFuncAttributeMaxDynamicSharedMemorySize, GSMEM);
    cudaFuncSetAttribute(gemm512<1>,  cudaFuncAttributeMaxDynamicSharedMemorySize, GSMEM);
    cudaFuncSetAttribute(scores_hmma, cudaFuncAttributeMaxDynamicSharedMemorySize, SSMEM);
    cudaFuncSetAttribute(av_hmma,     cudaFuncAttributeMaxDynamicSharedMemorySize, AVSMEM);

    bias_energy_kernel<<<5, 256>>>(tf, ts, gbias, energy);

    const size_t WN = (size_t)Dz * Dz;
    split_kernel<<<(Mz*Dz/4 + 1023)/1024, 256>>>(x, xh, xl, Mz*Dz/4);
    wsplit4_kernel<<<dim3((WN/4)/1024, 1, 4), 256>>>(Wq, Wk, Wv, Wo, wh, wl);

    gemm512<1><<<dim3(Dz/256, Mz/128, 3), 512, GSMEM>>>(
        xh, xl, wh, wl, bq, bk, bv, qh, ql, kh, kl, gv);

    tsplit_v<<<dim3(Lz/32, HDz/32, ZN), 256>>>(gv, vth, vtl);

    // scores: writes raw e + partial row sums (softmax kernel eliminated)
    scores_hmma<<<dim3(8, 8, ZN), 256, SSMEM>>>(qh, ql, kh, kl, gbias, attn, grs);

    // av: normalizes, writes attn output, computes ctx
    av_hmma<<<dim3(1, Lz/128, ZN), 256, AVSMEM>>>(attn, grs, vth, vtl, ch, cl);

    gemm512<0><<<dim3(Dz/256, Mz/128), 512, GSMEM>>>(
        ch, cl, wh + 3*WN, wl + 3*WN, bo, nullptr, nullptr,
        nullptr, nullptr, nullptr, nullptr, out);
}

// round 17
// speedup vs baseline: 1.1160x; 1.0185x over previous
#include <cuda_runtime.h>
#include <cuda_bf16.h>
#include <math.h>
#include <stdint.h>

#define Bz   4
#define Lz   1024
#define Dz   1024
#define Hz   16
#define HDz  64
#define Mz   (Bz*Lz)          // 4096
#define ORDERz 3
#define ZN   (Bz*Hz)          // 64

// ---------------- scratch (__device__ globals) ----------------------------------
__device__ __align__(16) float g_bias[Lz];
__device__ __align__(16) float g_rowsum[(size_t)ZN*Lz*8];   // per-CTA partial row sums

__device__ __align__(16) __nv_bfloat16 g_xh[Mz*Dz], g_xl[Mz*Dz];
__device__ __align__(16) __nv_bfloat16 g_wh[4][Dz*Dz], g_wl[4][Dz*Dz]; // q,k,v,o
__device__ __align__(16) __nv_bfloat16 g_qh[Mz*Dz], g_ql[Mz*Dz];       // (B,H,L,hd)
__device__ __align__(16) __nv_bfloat16 g_kh[Mz*Dz], g_kl[Mz*Dz];       // (B,H,L,hd)
__device__ __align__(16) __nv_bfloat16 g_vth[Mz*Dz], g_vtl[Mz*Dz];     // (B,H,hd,L)
__device__ __align__(16) __nv_bfloat16 g_ch[Mz*Dz], g_cl[Mz*Dz];       // ctx (B,L,D)

// ---------------- PTX helpers ----------------------------------------------------
__device__ __forceinline__ uint32_t smem_u32(const void* p) {
    uint32_t a;
    asm("{ .reg .u64 t; cvta.to.shared.u64 t, %1; cvt.u32.u64 %0, t; }" : "=r"(a) : "l"(p));
    return a;
}
__device__ __forceinline__ void cpasync16(uint32_t s, const void* g) {
    asm volatile("cp.async.cg.shared.global [%0], [%1], 16;" :: "r"(s), "l"(g));
}
#define CP_COMMIT()  asm volatile("cp.async.commit_group;" ::: "memory")
#define CP_WAIT2()   asm volatile("cp.async.wait_group 2;" ::: "memory")
#define CP_WAIT1()   asm volatile("cp.async.wait_group 1;" ::: "memory")
#define CP_WAIT0()   asm volatile("cp.async.wait_group 0;" ::: "memory")

__device__ __forceinline__ void stg_cs_f2(float* p, float2 v) {
    asm volatile("st.global.cs.v2.f32 [%0], {%1, %2};" :: "l"(p), "f"(v.x), "f"(v.y) : "memory");
}
__device__ __forceinline__ void stg_cs_f4(float* p, float4 v) {
    asm volatile("st.global.cs.v4.f32 [%0], {%1,%2,%3,%4};"
        :: "l"(p), "f"(v.x), "f"(v.y), "f"(v.z), "f"(v.w) : "memory");
}

__device__ __forceinline__ void hmma(float* d, const uint32_t* a, const uint32_t* b) {
    asm volatile(
        "mma.sync.aligned.m16n8k16.row.col.f32.bf16.bf16.f32 "
        "{%0,%1,%2,%3}, {%4,%5,%6,%7}, {%8,%9}, {%0,%1,%2,%3};"
        : "+f"(d[0]), "+f"(d[1]), "+f"(d[2]), "+f"(d[3])
        : "r"(a[0]), "r"(a[1]), "r"(a[2]), "r"(a[3]), "r"(b[0]), "r"(b[1]));
}
__device__ __forceinline__ void ldsm_x4(uint32_t* r, uint32_t saddr) {
    asm volatile("ldmatrix.sync.aligned.m8n8.x4.shared.b16 {%0,%1,%2,%3}, [%4];"
        : "=r"(r[0]), "=r"(r[1]), "=r"(r[2]), "=r"(r[3]) : "r"(saddr));
}
__device__ __forceinline__ void ldsm_x2(uint32_t* r, uint32_t saddr) {
    asm volatile("ldmatrix.sync.aligned.m8n8.x2.shared.b16 {%0,%1}, [%2];"
        : "=r"(r[0]), "=r"(r[1]) : "r"(saddr));
}

__device__ __forceinline__ __nv_bfloat162 split_hi2(float x, float y,
                                                    __nv_bfloat162& lo2) {
    __nv_bfloat16 hx = __float2bfloat16(x);
    __nv_bfloat16 hy = __float2bfloat16(y);
    lo2 = __nv_bfloat162(__float2bfloat16(x - __bfloat162float(hx)),
                         __float2bfloat16(y - __bfloat162float(hy)));
    return __nv_bfloat162(hx, hy);
}

__device__ __forceinline__ uint32_t a_ldsm_off(int lane, int RS) {
    return (uint32_t)((lane & 7) * RS + ((lane >> 3) & 1) * 8 * RS + ((lane >> 4) & 1) * 16);
}
__device__ __forceinline__ uint32_t b_ldsm_off(int lane, int RS) {
    const int l = lane & 15;
    return (uint32_t)((l & 7) * RS + ((l >> 3) & 1) * 16);
}

// ---------------- 512-thread, 128x256-tile, 3-stage HMMA GEMM ----------------------
// MODE 0: fp32 row-major out (out proj; W base pre-offset, zz=0).
// MODE 1: qkv. z=0/1 -> bf16 hi/lo head layout (Q/K); z=2 -> bf16 hi/lo transposed
//         (B,H,hd,L) V layout written directly (tsplit fused).
#define KC 32
#define ROWB 80
#define G_AM (128 * ROWB)
#define G_BM (256 * ROWB)
#define G_STAGE (2 * G_AM + 2 * G_BM)    // 61440
#define GSMEM (3 * G_STAGE)              // 184320

template<int MODE>
__global__ __launch_bounds__(512, 1) void gemm512(
    const __nv_bfloat16* __restrict__ Ah, const __nv_bfloat16* __restrict__ Al,
    const __nv_bfloat16* __restrict__ whBase, const __nv_bfloat16* __restrict__ wlBase,
    const float* __restrict__ bq, const float* __restrict__ bk, const float* __restrict__ bv,
    __nv_bfloat16* __restrict__ qh, __nv_bfloat16* __restrict__ ql,
    __nv_bfloat16* __restrict__ kh, __nv_bfloat16* __restrict__ kl,
    __nv_bfloat16* __restrict__ vth, __nv_bfloat16* __restrict__ vtl,
    float* __restrict__ Cf)
{
    extern __shared__ char sm[];
    const uint32_t sbase = smem_u32(sm);

    const int zz = (MODE == 1) ? blockIdx.z : 0;     // MODE 0: base pre-offset to Wo
    const size_t WN = (size_t)Dz * Dz;
    const __nv_bfloat16* Bh = whBase + (size_t)zz * WN;
    const __nv_bfloat16* Bl = wlBase + (size_t)zz * WN;
    const float* bias = (MODE == 0) ? bq : (blockIdx.z == 0) ? bq : (blockIdx.z == 1) ? bk : bv;

    const int K = Dz;
    const int tid  = threadIdx.x;
    const int warp = tid >> 5;
    const int lane = tid & 31;
    const int g = lane >> 2;
    const int t = lane & 3;
    const int wm = (warp >> 3) * 64;
    const int wn = (warp & 7) * 32;

    const int bm = blockIdx.y * 128;
    const int bn = blockIdx.x * 256;

    const __nv_bfloat16* tAh = Ah + (size_t)bm * K;
    const __nv_bfloat16* tAl = Al + (size_t)bm * K;
    const __nv_bfloat16* tBh = Bh + (size_t)bn * K;
    const __nv_bfloat16* tBl = Bl + (size_t)bn * K;

    const int ar = tid >> 2, as = tid & 3;

    const uint32_t aOff = a_ldsm_off(lane, ROWB);
    const uint32_t bOff = b_ldsm_off(lane, ROWB);

    auto prefetch = [&](int c, int stage) {
        const uint32_t sb = sbase + stage * G_STAGE;
        const int kb = c * KC;
        {
            const size_t go = (size_t)ar * K + kb + as * 8;
            const uint32_t so = ar * ROWB + as * 16;
            cpasync16(sb + so, tAh + go);
            cpasync16(sb + G_AM + so, tAl + go);
        }
        #pragma unroll
        for (int i = 0; i < 2; i++) {
            const int idx = tid + i * 512;
            const int row = idx >> 2, seg = idx & 3;
            const size_t go = (size_t)row * K + kb + seg * 8;
            const uint32_t so = row * ROWB + seg * 16;
            cpasync16(sb + 2 * G_AM + so, tBh + go);
            cpasync16(sb + 2 * G_AM + G_BM + so, tBl + go);
        }
    };

    float acc[4][4][4];
    #pragma unroll
    for (int i = 0; i < 4; i++)
        #pragma unroll
        for (int j = 0; j < 4; j++)
            #pragma unroll
            for (int k = 0; k < 4; k++) acc[i][j][k] = 0.0f;

    const int nch = K / KC;   // 32
    prefetch(0, 0); CP_COMMIT();
    prefetch(1, 1); CP_COMMIT();
    prefetch(2, 2); CP_COMMIT();

    for (int c = 0; c < nch; c++) {
        if (c + 2 < nch) { CP_WAIT2(); }
        else if (c + 1 < nch) { CP_WAIT1(); }
        else { CP_WAIT0(); }
        __syncthreads();

        const int st = c % 3;
        const uint32_t sb  = sbase + st * G_STAGE;
        const uint32_t sAh = sb;
        const uint32_t sAl = sb + G_AM;
        const uint32_t sBh = sb + 2 * G_AM;
        const uint32_t sBl = sb + 2 * G_AM + G_BM;

        #pragma unroll
        for (int kk = 0; kk < KC; kk += 16) {
            const uint32_t kb = kk * 2;

            uint32_t bH[4][2], bL[4][2];
            #pragma unroll
            for (int nt = 0; nt < 4; nt++) {
                const uint32_t ro = (wn + nt * 8) * ROWB + kb + bOff;
                ldsm_x2(bH[nt], sBh + ro);
                ldsm_x2(bL[nt], sBl + ro);
            }

            #pragma unroll
            for (int mt = 0; mt < 4; mt++) {
                const uint32_t ro = (wm + mt * 16) * ROWB + kb + aOff;
                uint32_t aH[4], aL[4];
                ldsm_x4(aH, sAh + ro);
                ldsm_x4(aL, sAl + ro);

                #pragma unroll
                for (int nt = 0; nt < 4; nt++) hmma(acc[mt][nt], aH, bH[nt]);
                #pragma unroll
                for (int nt = 0; nt < 4; nt++) hmma(acc[mt][nt], aH, bL[nt]);
                #pragma unroll
                for (int nt = 0; nt < 4; nt++) hmma(acc[mt][nt], aL, bH[nt]);
            }
        }

        __syncthreads();
        if (c + 3 < nch) { prefetch(c + 3, st); }
        CP_COMMIT();
    }

    #pragma unroll
    for (int mt = 0; mt < 4; mt++) {
        const int m0 = bm + wm + mt * 16 + g;
        #pragma unroll
        for (int nt = 0; nt < 4; nt++) {
            const int n0 = bn + wn + nt * 8 + 2 * t;
            const float b0 = bias[n0], b1 = bias[n0 + 1];
            float v0 = acc[mt][nt][0] + b0;
            float v1 = acc[mt][nt][1] + b1;
            float v2 = acc[mt][nt][2] + b0;
            float v3 = acc[mt][nt][3] + b1;
            if (MODE == 0) {
                *(float2*)&Cf[(size_t)m0 * Dz + n0]       = make_float2(v0, v1);
                *(float2*)&Cf[(size_t)(m0 + 8) * Dz + n0] = make_float2(v2, v3);
            } else {
                const int h = n0 >> 6, dd = n0 & 63;
                const int b = m0 >> 10, l = m0 & 1023;
                if (blockIdx.z == 2) {
                    // V: write bf16 hi/lo directly in transposed (B,H,hd,L) layout
                    const size_t base = ((size_t)(b * Hz + h) * HDz + dd) * Lz;
                    __nv_bfloat16 h0 = __float2bfloat16(v0);
                    __nv_bfloat16 h1 = __float2bfloat16(v1);
                    __nv_bfloat16 h2 = __float2bfloat16(v2);
                    __nv_bfloat16 h3 = __float2bfloat16(v3);
                    vth[base + l]          = h0;
                    vth[base + Lz + l]     = h1;
                    vth[base + l + 8]      = h2;
                    vth[base + Lz + l + 8] = h3;
                    vtl[base + l]          = __float2bfloat16(v0 - __bfloat162float(h0));
                    vtl[base + Lz + l]     = __float2bfloat16(v1 - __bfloat162float(h1));
                    vtl[base + l + 8]      = __float2bfloat16(v2 - __bfloat162float(h2));
                    vtl[base + Lz + l + 8] = __float2bfloat16(v3 - __bfloat162float(h3));
                } else {
                    __nv_bfloat16* Ch = (blockIdx.z == 0) ? qh : kh;
                    __nv_bfloat16* Cl = (blockIdx.z == 0) ? ql : kl;
                    const size_t i0 = (((size_t)(b * Hz + h) * Lz + l)     << 6) + dd;
                    const size_t i1 = (((size_t)(b * Hz + h) * Lz + l + 8) << 6) + dd;
                    __nv_bfloat162 lo;
                    __nv_bfloat162 hi = split_hi2(v0, v1, lo);
                    *(__nv_bfloat162*)&Ch[i0] = hi;
                    *(__nv_bfloat162*)&Cl[i0] = lo;
                    hi = split_hi2(v2, v3, lo);
                    *(__nv_bfloat162*)&Ch[i1] = hi;
                    *(__nv_bfloat162*)&Cl[i1] = lo;
                }
            }
        }
    }
}

// ---------------- scores HMMA: writes e=exp(score+bias), partial row sums ----------
#define SROW 144
#define SMAT (128 * SROW)
#define SSMEM (4 * SMAT)       // 73728 dynamic (+512 static)

__global__ __launch_bounds__(256, 2) void scores_hmma(
    const __nv_bfloat16* __restrict__ qh, const __nv_bfloat16* __restrict__ ql,
    const __nv_bfloat16* __restrict__ kh, const __nv_bfloat16* __restrict__ kl,
    const float* __restrict__ bias, float* __restrict__ attn,
    float* __restrict__ rowsum)
{
    extern __shared__ char sm[];
    const uint32_t sbase = smem_u32(sm);
    __shared__ float sums[128];

    const int tid  = threadIdx.x;
    const int warp = tid >> 5;
    const int lane = tid & 31;
    const int g = lane >> 2;
    const int t = lane & 3;
    const int wm = (warp >> 2) * 64;
    const int wn = (warp & 3) * 32;

    const int z  = blockIdx.z;
    const int bm = blockIdx.y * 128;
    const int bn = blockIdx.x * 128;

    const size_t zofs = (size_t)z * Lz * HDz;
    const __nv_bfloat16* pqh = qh + zofs + (size_t)bm * HDz;
    const __nv_bfloat16* pql = ql + zofs + (size_t)bm * HDz;
    const __nv_bfloat16* pkh = kh + zofs + (size_t)bn * HDz;
    const __nv_bfloat16* pkl = kl + zofs + (size_t)bn * HDz;

    #pragma unroll
    for (int i = 0; i < 4; i++) {
        const int idx = tid + i * 256;
        const int row = idx >> 3, seg = idx & 7;
        const uint32_t off = row * SROW + seg * 16;
        const size_t go = (size_t)row * HDz + seg * 8;
        cpasync16(sbase + 0 * SMAT + off, pqh + go);
        cpasync16(sbase + 1 * SMAT + off, pql + go);
        cpasync16(sbase + 2 * SMAT + off, pkh + go);
        cpasync16(sbase + 3 * SMAT + off, pkl + go);
    }
    if (tid < 128) sums[tid] = 0.0f;
    CP_COMMIT();
    CP_WAIT0();
    __syncthreads();

    float acc[4][4][4];
    #pragma unroll
    for (int i = 0; i < 4; i++)
        #pragma unroll
        for (int j = 0; j < 4; j++)
            #pragma unroll
            for (int k = 0; k < 4; k++) acc[i][j][k] = 0.0f;

    const uint32_t sQh = sbase;
    const uint32_t sQl = sbase + 1 * SMAT;
    const uint32_t sKh = sbase + 2 * SMAT;
    const uint32_t sKl = sbase + 3 * SMAT;

    const uint32_t aOff = a_ldsm_off(lane, SROW);
    const uint32_t bOff = b_ldsm_off(lane, SROW);

    #pragma unroll
    for (int kk = 0; kk < 64; kk += 16) {
        const uint32_t kb = kk * 2;

        uint32_t bH[4][2], bL[4][2];
        #pragma unroll
        for (int nt = 0; nt < 4; nt++) {
            const uint32_t ro = (wn + nt * 8) * SROW + kb + bOff;
            ldsm_x2(bH[nt], sKh + ro);
            ldsm_x2(bL[nt], sKl + ro);
        }

        #pragma unroll
        for (int mt = 0; mt < 4; mt++) {
            const uint32_t ro = (wm + mt * 16) * SROW + kb + aOff;
            uint32_t aH[4], aL[4];
            ldsm_x4(aH, sQh + ro);
            ldsm_x4(aL, sQl + ro);

            #pragma unroll
            for (int nt = 0; nt < 4; nt++) hmma(acc[mt][nt], aH, bH[nt]);
            #pragma unroll
            for (int nt = 0; nt < 4; nt++) hmma(acc[mt][nt], aH, bL[nt]);
            #pragma unroll
            for (int nt = 0; nt < 4; nt++) hmma(acc[mt][nt], aL, bH[nt]);
        }
    }

    float* attnZ = attn + (size_t)z * Lz * Lz;
    float pr0[4], pr1[4];
    #pragma unroll
    for (int mt = 0; mt < 4; mt++) { pr0[mt] = 0.0f; pr1[mt] = 0.0f; }

    #pragma unroll
    for (int mt = 0; mt < 4; mt++) {
        const int m0 = bm + wm + mt * 16 + g;
        #pragma unroll
        for (int nt = 0; nt < 4; nt++) {
            const int n0 = bn + wn + nt * 8 + 2 * t;
            const float b0 = bias[n0], b1 = bias[n0 + 1];
            const float e0 = __expf(acc[mt][nt][0] * 0.125f + b0);
            const float e1 = __expf(acc[mt][nt][1] * 0.125f + b1);
            const float e2 = __expf(acc[mt][nt][2] * 0.125f + b0);
            const float e3 = __expf(acc[mt][nt][3] * 0.125f + b1);
            stg_cs_f2(&attnZ[(size_t)m0 * Lz + n0],       make_float2(e0, e1));
            stg_cs_f2(&attnZ[(size_t)(m0 + 8) * Lz + n0], make_float2(e2, e3));
            pr0[mt] += e0 + e1;
            pr1[mt] += e2 + e3;
        }
    }
    #pragma unroll
    for (int o = 1; o <= 2; o <<= 1) {
        #pragma unroll
        for (int mt = 0; mt < 4; mt++) {
            pr0[mt] += __shfl_xor_sync(0xFFFFFFFFu, pr0[mt], o);
            pr1[mt] += __shfl_xor_sync(0xFFFFFFFFu, pr1[mt], o);
        }
    }
    if (t == 0) {
        #pragma unroll
        for (int mt = 0; mt < 4; mt++) {
            atomicAdd(&sums[wm + mt * 16 + g],     pr0[mt]);
            atomicAdd(&sums[wm + mt * 16 + g + 8], pr1[mt]);
        }
    }
    __syncthreads();
    if (tid < 128)
        rowsum[((size_t)z * Lz + bm + tid) * 8 + (bn >> 7)] = sums[tid];
}

// ---------------- AV HMMA: normalizes raw e, writes attn output, does AV ------------
#define AVF_ROW 144
#define AVF_BYTES (128 * AVF_ROW)
#define AV_HROW 80
#define AV_HBYTES (128 * AV_HROW)
#define AV_VBYTES (64 * AV_HROW)
#define AV_AH_OFF (2 * AVF_BYTES)
#define AV_AL_OFF (AV_AH_OFF + AV_HBYTES)
#define AV_V_OFF  (AV_AL_OFF + AV_HBYTES)
#define AVSMEM (AV_V_OFF + 4 * AV_VBYTES)    // 77824 dynamic (+512 static)

__global__ __launch_bounds__(256, 2) void av_hmma(
    float* __restrict__ attn, const float* __restrict__ rowsum,
    const __nv_bfloat16* __restrict__ vth, const __nv_bfloat16* __restrict__ vtl,
    __nv_bfloat16* __restrict__ Ch, __nv_bfloat16* __restrict__ Cl)
{
    extern __shared__ char sm[];
    const uint32_t sbase = smem_u32(sm);
    __shared__ float inv_s[128];

    const int tid  = threadIdx.x;
    const int warp = tid >> 5;
    const int lane = tid & 31;
    const int g = lane >> 2;
    const int t = lane & 3;
    const int wm = (warp >> 1) * 32;
    const int wn = (warp & 1) * 32;

    const int z  = blockIdx.z;
    const int bm = blockIdx.y * 128;

    float* pA = attn + (size_t)z * Lz * Lz + (size_t)bm * Lz;
    const __nv_bfloat16* pvh = vth + (size_t)z * HDz * Lz;
    const __nv_bfloat16* pvl = vtl + (size_t)z * HDz * Lz;

    const uint32_t sAh = sbase + AV_AH_OFF;
    const uint32_t sAl = sbase + AV_AL_OFF;
    const uint32_t sV  = sbase + AV_V_OFF;

    const uint32_t aOff = a_ldsm_off(lane, AV_HROW);
    const uint32_t bOff = b_ldsm_off(lane, AV_HROW);

    const int arow = tid >> 3, aseg = tid & 7;
    const int vrow = tid >> 2, vseg = tid & 3;

    if (tid < 128) {
        const float* rs = rowsum + ((size_t)z * Lz + bm + tid) * 8;
        float s = (rs[0] + rs[1]) + (rs[2] + rs[3]) + (rs[4] + rs[5]) + (rs[6] + rs[7]);
        inv_s[tid] = 1.0f / s;
    }

    auto prefetch = [&](int c, int stage) {
        const uint32_t sa = sbase + stage * AVF_BYTES;
        #pragma unroll
        for (int i = 0; i < 4; i++) {
            const int row = arow + i * 32;
            cpasync16(sa + row * AVF_ROW + aseg * 16,
                      pA + (size_t)row * Lz + c * 32 + aseg * 4);
        }
        const uint32_t sv = sV + stage * (2 * AV_VBYTES);
        cpasync16(sv + vrow * AV_HROW + vseg * 16,
                  pvh + (size_t)vrow * Lz + c * 32 + vseg * 8);
        cpasync16(sv + AV_VBYTES + vrow * AV_HROW + vseg * 16,
                  pvl + (size_t)vrow * Lz + c * 32 + vseg * 8);
    };

    float acc[2][4][4];
    #pragma unroll
    for (int i = 0; i < 2; i++)
        #pragma unroll
        for (int j = 0; j < 4; j++)
            #pragma unroll
            for (int k = 0; k < 4; k++) acc[i][j][k] = 0.0f;

    const int nch = Lz / 32;
    prefetch(0, 0); CP_COMMIT();
    prefetch(1, 1); CP_COMMIT();

    for (int c = 0; c < nch; c++) {
        if (c + 1 < nch) { CP_WAIT1(); } else { CP_WAIT0(); }
        __syncthreads();

        const uint32_t sa = sbase + (c & 1) * AVF_BYTES;
        #pragma unroll
        for (int i = 0; i < 4; i++) {
            const int row = arow + i * 32;
            const float4 v = *(const float4*)(sm + (sa - sbase) + row * AVF_ROW + aseg * 16);
            const float is = inv_s[row];
            const float4 w = make_float4(v.x * is, v.y * is, v.z * is, v.w * is);
            stg_cs_f4(pA + (size_t)row * Lz + c * 32 + aseg * 4, w);
            __nv_bfloat162 lo0, lo1;
            __nv_bfloat162 hi0 = split_hi2(w.x, w.y, lo0);
            __nv_bfloat162 hi1 = split_hi2(w.z, w.w, lo1);
            uint2 h8, l8;
            h8.x = *reinterpret_cast<uint32_t*>(&hi0);
            h8.y = *reinterpret_cast<uint32_t*>(&hi1);
            l8.x = *reinterpret_cast<uint32_t*>(&lo0);
            l8.y = *reinterpret_cast<uint32_t*>(&lo1);
            *(uint2*)(sm + AV_AH_OFF + row * AV_HROW + aseg * 8) = h8;
            *(uint2*)(sm + AV_AL_OFF + row * AV_HROW + aseg * 8) = l8;
        }
        __syncthreads();

        const uint32_t sVh = sV + (c & 1) * (2 * AV_VBYTES);
        const uint32_t sVl = sVh + AV_VBYTES;

        #pragma unroll
        for (int kk = 0; kk < 32; kk += 16) {
            const uint32_t kb = kk * 2;

            uint32_t bH[4][2], bL[4][2];
            #pragma unroll
            for (int nt = 0; nt < 4; nt++) {
                const uint32_t ro = (wn + nt * 8) * AV_HROW + kb + bOff;
                ldsm_x2(bH[nt], sVh + ro);
                ldsm_x2(bL[nt], sVl + ro);
            }

            #pragma unroll
            for (int mt = 0; mt < 2; mt++) {
                const uint32_t ro = (wm + mt * 16) * AV_HROW + kb + aOff;
                uint32_t aH[4], aL[4];
                ldsm_x4(aH, sAh + ro);
                ldsm_x4(aL, sAl + ro);

                #pragma unroll
                for (int nt = 0; nt < 4; nt++) hmma(acc[mt][nt], aH, bH[nt]);
                #pragma unroll
                for (int nt = 0; nt < 4; nt++) hmma(acc[mt][nt], aH, bL[nt]);
                #pragma unroll
                for (int nt = 0; nt < 4; nt++) hmma(acc[mt][nt], aL, bH[nt]);
            }
        }

        __syncthreads();
        if (c + 2 < nch) { prefetch(c + 2, (c & 1)); CP_COMMIT(); }
        else { CP_COMMIT(); }
    }

    const int b = z >> 4, h = z & 15;
    #pragma unroll
    for (int mt = 0; mt < 2; mt++) {
        const int m0 = bm + wm + mt * 16 + g;
        #pragma unroll
        for (int nt = 0; nt < 4; nt++) {
            const int n0 = wn + nt * 8 + 2 * t;
            const size_t i0 = ((size_t)(b * Lz + m0)     << 10) + h * HDz + n0;
            const size_t i1 = ((size_t)(b * Lz + m0 + 8) << 10) + h * HDz + n0;
            __nv_bfloat162 lo;
            __nv_bfloat162 hi = split_hi2(acc[mt][nt][0], acc[mt][nt][1], lo);
            *(__nv_bfloat162*)&Ch[i0] = hi;
            *(__nv_bfloat162*)&Cl[i0] = lo;
            hi = split_hi2(acc[mt][nt][2], acc[mt][nt][3], lo);
            *(__nv_bfloat162*)&Ch[i1] = hi;
            *(__nv_bfloat162*)&Cl[i1] = lo;
        }
    }
}

// ---------------- all splits in one launch: z<4 -> W[z], z>=4 -> x quarter ----------
__global__ __launch_bounds__(256) void split_all_kernel(
    const float* __restrict__ W0, const float* __restrict__ W1,
    const float* __restrict__ W2, const float* __restrict__ W3,
    const float* __restrict__ x,
    __nv_bfloat16* __restrict__ wh, __nv_bfloat16* __restrict__ wl,
    __nv_bfloat16* __restrict__ xh, __nv_bfloat16* __restrict__ xl)
{
    const int z = blockIdx.z;
    const size_t WN = (size_t)Dz * Dz;
    const float* src;
    __nv_bfloat162* H;
    __nv_bfloat162* L;
    if (z < 4) {
        src = (z == 0) ? W0 : (z == 1) ? W1 : (z == 2) ? W2 : W3;
        H = (__nv_bfloat162*)(wh + z * WN);
        L = (__nv_bfloat162*)(wl + z * WN);
    } else {
        src = x + (size_t)(z - 4) * WN;
        H = (__nv_bfloat162*)(xh + (size_t)(z - 4) * WN);
        L = (__nv_bfloat162*)(xl + (size_t)(z - 4) * WN);
    }
    int i = blockIdx.x * (blockDim.x * 4) + threadIdx.x;
    #pragma unroll
    for (int u = 0; u < 4; u++, i += 256) {
        float4 v = ((const float4*)src)[i];
        __nv_bfloat162 l2;
        H[i*2+0] = split_hi2(v.x, v.y, l2); L[i*2+0] = l2;
        H[i*2+1] = split_hi2(v.z, v.w, l2); L[i*2+1] = l2;
    }
}

__global__ void bias_energy_kernel(const float* __restrict__ field,
                                   const float* __restrict__ strength,
                                   float* __restrict__ bias,
                                   float* __restrict__ e)
{
    if (blockIdx.x == 4) {
        if (threadIdx.x == 0)
            e[0] = (strength[0] * strength[0] + strength[1] * strength[1] +
                    strength[2] * strength[2]) * (1.0f / 3.0f);
        return;
    }
    int m = blockIdx.x * blockDim.x + threadIdx.x;
    if (m < Lz) {
        const float pi = 3.14159265358979323846f;
        float acc = 0.0f;
        #pragma unroll
        for (int i = 0; i < ORDERz; i++) {
            float sig = 1.0f / (1.0f + expf(-field[i * Lz + m]));
            acc += strength[i] * sinf((float)m * (float)(i + 1) * pi / (float)Lz) * sig;
        }
        bias[m] = acc;
    }
}

// ---------------- launch ----------------------------------------------------------------
extern "C" void kernel_launch(void* const* d_in, const int* in_sizes, int n_in,
                              void* d_out, int out_size)
{
    const float* x  = (const float*)d_in[0];
    const float* Wq = (const float*)d_in[1];
    const float* bq = (const float*)d_in[2];
    const float* Wk = (const float*)d_in[3];
    const float* bk = (const float*)d_in[4];
    const float* Wv = (const float*)d_in[5];
    const float* bv = (const float*)d_in[6];
    const float* Wo = (const float*)d_in[7];
    const float* bo = (const float*)d_in[8];
    const float* tf = (const float*)d_in[9];
    const float* ts = (const float*)d_in[10];

    float* out    = (float*)d_out;
    float* attn   = out + (size_t)Bz * Lz * Dz;
    float* energy = attn + (size_t)ZN * Lz * Lz;

    float *gbias, *grs;
    cudaGetSymbolAddress((void**)&gbias, g_bias);
    cudaGetSymbolAddress((void**)&grs,   g_rowsum);

    __nv_bfloat16 *xh, *xl, *wh, *wl, *qh, *ql, *kh, *kl, *vth, *vtl, *ch, *cl;
    cudaGetSymbolAddress((void**)&xh,  g_xh);
    cudaGetSymbolAddress((void**)&xl,  g_xl);
    cudaGetSymbolAddress((void**)&wh,  g_wh);
    cudaGetSymbolAddress((void**)&wl,  g_wl);
    cudaGetSymbolAddress((void**)&qh,  g_qh);
    cudaGetSymbolAddress((void**)&ql,  g_ql);
    cudaGetSymbolAddress((void**)&kh,  g_kh);
    cudaGetSymbolAddress((void**)&kl,  g_kl);
    cudaGetSymbolAddress((void**)&vth, g_vth);
    cudaGetSymbolAddress((void**)&vtl, g_vtl);
    cudaGetSymbolAddress((void**)&ch,  g_ch);
    cudaGetSymbolAddress((void**)&cl,  g_cl);

    cudaFuncSetAttribute(gemm512<0>,  cudaFuncAttributeMaxDynamicSharedMemorySize, GSMEM);
    cudaFuncSetAttribute(gemm512<1>,  cudaFuncAttributeMaxDynamicSharedMemorySize, GSMEM);
    cudaFuncSetAttribute(scores_hmma, cudaFuncAttributeMaxDynamicSharedMemorySize, SSMEM);
    cudaFuncSetAttribute(av_hmma,     cudaFuncAttributeMaxDynamicSharedMemorySize, AVSMEM);

    bias_energy_kernel<<<5, 256>>>(tf, ts, gbias, energy);

    const size_t WN = (size_t)Dz * Dz;
    // all fp32->bf16 hi/lo splits in one launch (4 weights + 4 x-quarters)
    split_all_kernel<<<dim3((WN/4)/1024, 1, 8), 256>>>(Wq, Wk, Wv, Wo, x, wh, wl, xh, xl);

    // merged QKV projections; z=2 (V) writes transposed bf16 hi/lo directly
    gemm512<1><<<dim3(Dz/256, Mz/128, 3), 512, GSMEM>>>(
        xh, xl, wh, wl, bq, bk, bv, qh, ql, kh, kl, vth, vtl, nullptr);

    // scores: raw e + partial row sums
    scores_hmma<<<dim3(8, 8, ZN), 256, SSMEM>>>(qh, ql, kh, kl, gbias, attn, grs);

    // av: normalizes, writes attn output, computes ctx
    av_hmma<<<dim3(1, Lz/128, ZN), 256, AVSMEM>>>(attn, grs, vth, vtl, ch, cl);

    gemm512<0><<<dim3(Dz/256, Mz/128), 512, GSMEM>>>(
        ch, cl, wh + 3*WN, wl + 3*WN, bo, nullptr, nullptr,
        nullptr, nullptr, nullptr, nullptr, nullptr, nullptr, out);
}